// round 3
// baseline (speedup 1.0000x reference)
#include <cuda_runtime.h>
#include <math.h>

// Problem dims
#define NTOK 16384          // B*S = 16*1024
#define DQK  192            // 3*F
#define SEQ  1024

// ---------------- device scratch (allocation-free) ----------------
__device__ float  g_q[NTOK * DQK];
__device__ float  g_k[NTOK * DQK];
__device__ float  g_v[NTOK * DQK];
__device__ float2 g_U[48][16][16];   // [qkv*16+split][row][col]

// ---------------- f32x2 packed helpers ----------------
__device__ __forceinline__ unsigned long long pack2(float lo, float hi) {
    unsigned long long r;
    asm("mov.b64 %0, {%1,%2};" : "=l"(r) : "f"(lo), "f"(hi));
    return r;
}
__device__ __forceinline__ void ffma2(unsigned long long& d, unsigned long long a, unsigned long long b) {
    asm("fma.rn.f32x2 %0, %1, %2, %0;" : "+l"(d) : "l"(a), "l"(b));
}
__device__ __forceinline__ float2 unpack2(unsigned long long v) {
    float2 r;
    asm("mov.b64 {%0,%1}, %2;" : "=f"(r.x), "=f"(r.y) : "l"(v));
    return r;
}

// ---------------- complex gate helpers (register state) ----------------
__device__ __forceinline__ void gate_rx(float2* v, int w, float ch, float sh) {
    int bit = 8 >> w;
#pragma unroll
    for (int n = 0; n < 16; n++) if (!(n & bit)) {
        float2 a = v[n], b = v[n | bit];
        v[n]       = make_float2(ch * a.x + sh * b.y, ch * a.y - sh * b.x);
        v[n | bit] = make_float2(ch * b.x + sh * a.y, ch * b.y - sh * a.x);
    }
}
__device__ __forceinline__ void gate_ry(float2* v, int w, float ch, float sh) {
    int bit = 8 >> w;
#pragma unroll
    for (int n = 0; n < 16; n++) if (!(n & bit)) {
        float2 a = v[n], b = v[n | bit];
        v[n]       = make_float2(ch * a.x - sh * b.x, ch * a.y - sh * b.y);
        v[n | bit] = make_float2(sh * a.x + ch * b.x, sh * a.y + ch * b.y);
    }
}
__device__ __forceinline__ void gate_rz(float2* v, int w, float ch, float sh) {
    int bit = 8 >> w;
#pragma unroll
    for (int n = 0; n < 16; n++) {
        float2 a = v[n];
        if (n & bit) v[n] = make_float2(ch * a.x - sh * a.y, ch * a.y + sh * a.x);
        else         v[n] = make_float2(ch * a.x + sh * a.y, ch * a.y - sh * a.x);
    }
}
__device__ __forceinline__ void gate_h(float2* v, int w) {
    int bit = 8 >> w;
    const float r = 0.70710678118654752440f;
#pragma unroll
    for (int n = 0; n < 16; n++) if (!(n & bit)) {
        float2 a = v[n], b = v[n | bit];
        v[n]       = make_float2(r * (a.x + b.x), r * (a.y + b.y));
        v[n | bit] = make_float2(r * (a.x - b.x), r * (a.y - b.y));
    }
}
__device__ __forceinline__ void gate_crx(float2* v, int c, int g, float ch, float sh) {
    int bc = 8 >> c, bg = 8 >> g;
#pragma unroll
    for (int n = 0; n < 16; n++) if ((n & bc) && !(n & bg)) {
        float2 a = v[n], b = v[n | bg];
        v[n]      = make_float2(ch * a.x + sh * b.y, ch * a.y - sh * b.x);
        v[n | bg] = make_float2(ch * b.x + sh * a.y, ch * b.y - sh * a.x);
    }
}
__device__ __forceinline__ void gate_cphase(float2* v, int j, int i, float phi) {
    int bj = 8 >> j, bi = 8 >> i;
    float sp, cp;
    sincosf(phi, &sp, &cp);
#pragma unroll
    for (int n = 0; n < 16; n++) if ((n & bj) && (n & bi)) {
        float2 a = v[n];
        v[n] = make_float2(cp * a.x - sp * a.y, cp * a.y + sp * a.x);
    }
}
__device__ __forceinline__ void gate_iswap(float2* v, int w0, int w1) {
    int b0 = 8 >> w0, b1 = 8 >> w1;
#pragma unroll
    for (int n = 0; n < 16; n++) if (!(n & b0) && (n & b1)) {
        int m = (n | b0) & ~b1;
        float2 a = v[n], b = v[m];
        v[n] = make_float2(-b.y, b.x);
        v[m] = make_float2(-a.y, a.x);
    }
}
__device__ __forceinline__ void gate_swap(float2* v, int w0, int w1) {
    int b0 = 8 >> w0, b1 = 8 >> w1;
#pragma unroll
    for (int n = 0; n < 16; n++) if (!(n & b0) && (n & b1)) {
        int m = (n | b0) & ~b1;
        float2 t = v[n]; v[n] = v[m]; v[m] = t;
    }
}

// ---------------- Kernel A: build 48 fixed 16x16 unitaries ----------------
__global__ void __launch_bounds__(16) build_U_kernel(const float* __restrict__ W,
                                                     const float* __restrict__ EW,
                                                     const float* __restrict__ TW) {
    const int u   = blockIdx.x;
    const int col = threadIdx.x;
    const float* w  = W  + u * 12;
    const float* ew = EW + u * 12;
    const float* tw = TW + u * 12;

    float2 v[16];
#pragma unroll
    for (int n = 0; n < 16; n++) v[n] = make_float2(n == col ? 1.f : 0.f, 0.f);

    const float PI = 3.14159265358979323846f;

#pragma unroll
    for (int L = 0; L < 3; L++) {
#pragma unroll
        for (int i = 0; i < 4; i++) {
            float sh, ch;
            sincosf(0.5f * w[L * 4 + i], &sh, &ch);
            gate_rx(v, i, ch, sh);
            gate_ry(v, i, ch, sh);
            gate_rz(v, i, ch, sh);
        }
#pragma unroll
        for (int i = 0; i < 4; i++) {
            float sh, ch;
            sincosf(0.5f * ew[L * 4 + i], &sh, &ch);
            gate_crx(v, i, (i + 2) & 3, ch, sh);
            gate_crx(v, i, (i + 3) & 3, ch, sh);
        }
        gate_iswap(v, 0, 1); gate_iswap(v, 1, 2); gate_iswap(v, 2, 3); gate_iswap(v, 3, 0);
        { float2 t = v[12]; v[12] = v[14]; v[14] = t;
          t = v[13]; v[13] = v[15]; v[15] = t; }
#pragma unroll
        for (int i = 0; i < 3; i++) {
            float sh, ch;
            sincosf(0.5f * tw[L * 4 + i], &sh, &ch);
            gate_crx(v, i, i + 1, ch, sh);
        }
        { float sh, ch; sincosf(0.5f * tw[L * 4 + 3], &sh, &ch); gate_crx(v, 3, 0, ch, sh); }
#pragma unroll
        for (int i = 0; i < 4; i++) gate_h(v, i);
#pragma unroll
        for (int i = 1; i < 4; i++)
#pragma unroll
            for (int j = 0; j < i; j++)
                gate_cphase(v, j, i, PI / (float)(1 << (i - j)));
        gate_swap(v, 0, 3); gate_swap(v, 1, 2);
#pragma unroll
        for (int i = 0; i < 4; i++) {
            gate_h(v, i);
#pragma unroll
            for (int j = 0; j < i; j++)
                gate_cphase(v, j, i, -PI / (float)(1 << (i - j)));
        }
    }

#pragma unroll
    for (int n = 0; n < 16; n++) g_U[u][n][col] = v[n];
}

// ---------------- Kernel B: per-token QKV via packed 16x16 complex matvec ----------------
__global__ void __launch_bounds__(128) qkv_kernel(const float* __restrict__ x) {
    const int sp  = blockIdx.x;
    const int t0  = blockIdx.y * 128;
    const int tid = threadIdx.x;
    const int t   = t0 + tid;

    __shared__ unsigned long long sUp[3][16][16];
    __shared__ unsigned long long sUm[3][16][16];
    __shared__ float so[128][13];

    for (int r0 = tid; r0 < 768; r0 += 128) {
        int q = r0 >> 8, rem = r0 & 255;
        float2 Uv = g_U[q * 16 + sp][rem >> 4][rem & 15];
        sUp[q][rem >> 4][rem & 15] = pack2(Uv.x, Uv.x);
        sUm[q][rem >> 4][rem & 15] = pack2(-Uv.y, Uv.y);
    }
    __syncthreads();

    const float4 xv = reinterpret_cast<const float4*>(x)[(size_t)t * 16 + sp];
    float cs[4], sn[4];
    sincosf(0.5f * xv.x, &sn[0], &cs[0]);
    sincosf(0.5f * xv.y, &sn[1], &cs[1]);
    sincosf(0.5f * xv.z, &sn[2], &cs[2]);
    sincosf(0.5f * xv.w, &sn[3], &cs[3]);

    unsigned long long ep[16], er[16];
#pragma unroll
    for (int n = 0; n < 16; n++) {
        float m = (n & 8 ? sn[0] : cs[0]) * (n & 4 ? sn[1] : cs[1]) *
                  (n & 2 ? sn[2] : cs[2]) * (n & 1 ? sn[3] : cs[3]);
        int pc = __popc(n) & 3;
        float ex = (pc == 0) ? m : (pc == 2) ? -m : 0.f;
        float ey = (pc == 1) ? -m : (pc == 3) ? m : 0.f;
        ep[n] = pack2(ex, ey);
        er[n] = pack2(ey, ex);
    }

#pragma unroll
    for (int q = 0; q < 3; q++) {
        float2 psi[16];
#pragma unroll
        for (int r = 0; r < 16; r++) {
            unsigned long long acc = pack2(0.f, 0.f);
#pragma unroll
            for (int k = 0; k < 16; k++) {
                ffma2(acc, sUp[q][r][k], ep[k]);
                ffma2(acc, sUm[q][r][k], er[k]);
            }
            psi[r] = unpack2(acc);
        }
        float o[12];
#pragma unroll
        for (int w = 0; w < 4; w++) {
            int bit = 8 >> w;
            float z = 0.f, xr = 0.f, yi = 0.f;
#pragma unroll
            for (int n = 0; n < 16; n++) {
                if (n & bit) continue;
                float2 a = psi[n], b = psi[n | bit];
                z  += (a.x * a.x + a.y * a.y) - (b.x * b.x + b.y * b.y);
                xr += a.x * b.x + a.y * b.y;
                yi += a.x * b.y - a.y * b.x;
            }
            o[w] = z; o[4 + w] = 2.f * xr; o[8 + w] = 2.f * yi;
        }
        __syncthreads();
#pragma unroll
        for (int m = 0; m < 12; m++) so[tid][m] = o[m];
        __syncthreads();
        float* base = (q == 0 ? g_q : (q == 1 ? g_k : g_v)) + (size_t)t0 * DQK + sp * 12;
        for (int idx = tid; idx < 1536; idx += 128) {
            int row = idx / 12, col = idx - row * 12;
            base[(size_t)row * DQK + col] = so[row][col];
        }
    }
}

// ---------------- Fused attention: scores + softmax + O=AV + LayerNorm ----------------
// Block: 32 query rows of one batch. 256 threads.
// Smem layout (bytes):
//  sS  @0       : 32*1024*4      = 131072   score/prob strip
//  sQ2 @131072  : 192*36*8       = 55296    Q as (q,q) f32x2 pairs, [k][m] pad36
//  sK  @186368  : 2*32*132*4     = 33792    K tiles [buf][k][n] pad132
//  sV  @131072  : 2*32*196*4     = 50176    V tiles (reuses sQ2+sK region in phase 3)
#define FUSED_SMEM 220160

__global__ void __launch_bounds__(256) fused_attn_kernel(float* __restrict__ attn,
                                                         float* __restrict__ Oout,
                                                         const float* __restrict__ gamma,
                                                         const float* __restrict__ beta) {
    extern __shared__ __align__(16) char smem[];
    float*              sS  = (float*)smem;
    unsigned long long* sQ2 = (unsigned long long*)(smem + 131072);
    float*              sK  = (float*)(smem + 186368);
    float*              sV  = (float*)(smem + 131072);

    const int b   = blockIdx.y;
    const int m0  = blockIdx.x * 32;
    const int tid = threadIdx.x;
    const int lane = tid & 31;
    const int wid  = tid >> 5;
    const int tm   = wid * 4;           // 4 m-rows per warp
    const int tn2  = lane * 2;          // ULL index into 128-wide n strip (floats 4*lane)

    const float* Q = g_q + ((size_t)b * SEQ + m0) * DQK;
    const float* K = g_k + (size_t)b * SEQ * DQK;
    const float* V = g_v + (size_t)b * SEQ * DQK;

    // ---- fill sQ2: Q[32][192] -> (q,q) pairs at [k][m], pad 36 ----
#pragma unroll
    for (int i = 0; i < 6; i++) {
        int idx = i * 256 + tid;
        int m = idx / 48, j = idx % 48;
        float4 qv = *reinterpret_cast<const float4*>(&Q[(size_t)m * DQK + j * 4]);
        sQ2[(j * 4 + 0) * 36 + m] = pack2(qv.x, qv.x);
        sQ2[(j * 4 + 1) * 36 + m] = pack2(qv.y, qv.y);
        sQ2[(j * 4 + 2) * 36 + m] = pack2(qv.z, qv.z);
        sQ2[(j * 4 + 3) * 36 + m] = pack2(qv.w, qv.w);
    }

    // ---- phase 1: S = Q K^T * 0.5 into sS ----
    // 48 tiles: c -> n0=(c/6)*128, k0=(c%6)*32 ; tile = sK[buf][32k][128n]
    float4 pk[4];
    int ldn[4], ldj[4];
#pragma unroll
    for (int i = 0; i < 4; i++) {
        int idx = i * 256 + tid;
        ldn[i] = idx >> 3; ldj[i] = idx & 7;
    }

#define K_LOAD(c) { int n0_ = ((c) / 6) * 128, k0_ = ((c) % 6) * 32; \
    pk[0] = *reinterpret_cast<const float4*>(&K[(size_t)(n0_ + ldn[0]) * DQK + k0_ + ldj[0] * 4]); \
    pk[1] = *reinterpret_cast<const float4*>(&K[(size_t)(n0_ + ldn[1]) * DQK + k0_ + ldj[1] * 4]); \
    pk[2] = *reinterpret_cast<const float4*>(&K[(size_t)(n0_ + ldn[2]) * DQK + k0_ + ldj[2] * 4]); \
    pk[3] = *reinterpret_cast<const float4*>(&K[(size_t)(n0_ + ldn[3]) * DQK + k0_ + ldj[3] * 4]); }

#define K_STORE(buf) { float* dst = sK + (buf) * 4224; \
    _Pragma("unroll") \
    for (int i_ = 0; i_ < 4; i_++) { \
        float* d = dst + (ldj[i_] * 4) * 132 + ldn[i_]; \
        d[0] = pk[i_].x; d[132] = pk[i_].y; d[264] = pk[i_].z; d[396] = pk[i_].w; } }

    unsigned long long acc[4][2];
#pragma unroll
    for (int i = 0; i < 4; i++) { acc[i][0] = 0ull; acc[i][1] = 0ull; }

    K_LOAD(0); __syncthreads(); K_STORE(0); __syncthreads();

    for (int c = 0; c < 48; c++) {
        int buf = c & 1;
        if (c < 47) K_LOAD(c + 1);
        int k0 = (c % 6) * 32;
        const float* kt = sK + buf * 4224;
#pragma unroll
        for (int kk = 0; kk < 32; kk++) {
            const unsigned long long* aq = sQ2 + (size_t)(k0 + kk) * 36 + tm;
            unsigned long long a0 = aq[0], a1 = aq[1], a2 = aq[2], a3 = aq[3];
            const unsigned long long* br = reinterpret_cast<const unsigned long long*>(kt + kk * 132);
            unsigned long long b0 = br[tn2], b1 = br[tn2 + 1];
            ffma2(acc[0][0], a0, b0); ffma2(acc[0][1], a0, b1);
            ffma2(acc[1][0], a1, b0); ffma2(acc[1][1], a1, b1);
            ffma2(acc[2][0], a2, b0); ffma2(acc[2][1], a2, b1);
            ffma2(acc[3][0], a3, b0); ffma2(acc[3][1], a3, b1);
        }
        __syncthreads();
        if (c < 47) { K_STORE(buf ^ 1); __syncthreads(); }
        if (c % 6 == 5) {
            int n0 = (c / 6) * 128;
#pragma unroll
            for (int i = 0; i < 4; i++) {
                float2 lo = unpack2(acc[i][0]), hi = unpack2(acc[i][1]);
                *reinterpret_cast<float4*>(&sS[(tm + i) * 1024 + n0 + lane * 4]) =
                    make_float4(0.5f * lo.x, 0.5f * lo.y, 0.5f * hi.x, 0.5f * hi.y);
                acc[i][0] = 0ull; acc[i][1] = 0ull;
            }
        }
    }
    __syncthreads();

    // ---- phase 2: softmax rows in smem, write probs to gmem attn ----
    {
        float* row = sS + (wid * 4) * 1024;           // warp handles rows tm..tm+3
        float* arow = attn + ((size_t)(b * SEQ + m0 + tm)) * SEQ;
#pragma unroll
        for (int i = 0; i < 4; i++) {
            float vals[32];
            float mx = -1e30f;
#pragma unroll
            for (int j = 0; j < 32; j++) {
                vals[j] = row[i * 1024 + lane + 32 * j];
                mx = fmaxf(mx, vals[j]);
            }
#pragma unroll
            for (int o = 16; o; o >>= 1) mx = fmaxf(mx, __shfl_xor_sync(0xffffffffu, mx, o));
            float s = 0.f;
#pragma unroll
            for (int j = 0; j < 32; j++) {
                vals[j] = exp2f((vals[j] - mx) * 1.4426950408889634f);
                s += vals[j];
            }
#pragma unroll
            for (int o = 16; o; o >>= 1) s += __shfl_xor_sync(0xffffffffu, s, o);
            float inv = 1.f / s;
#pragma unroll
            for (int j = 0; j < 32; j++) {
                float p = vals[j] * inv;
                row[i * 1024 + lane + 32 * j] = p;
                arow[(size_t)i * SEQ + lane + 32 * j] = p;
            }
        }
    }
    __syncthreads();

    // ---- phase 3: O = P(32x1024, smem) @ V(1024x192) ----
    const int tn3 = lane * 3;           // ULL index (floats 6*lane)
    float4 pv[6];
    int vkk[6], vj[6];
#pragma unroll
    for (int i = 0; i < 6; i++) {
        int idx = i * 256 + tid;
        vkk[i] = idx / 48; vj[i] = idx % 48;
    }

#define V_LOAD(t) { int k0_ = (t) * 32; \
    _Pragma("unroll") \
    for (int i_ = 0; i_ < 6; i_++) \
        pv[i_] = *reinterpret_cast<const float4*>(&V[(size_t)(k0_ + vkk[i_]) * DQK + vj[i_] * 4]); }

#define V_STORE(buf) { float* dst = sV + (buf) * 6272; \
    _Pragma("unroll") \
    for (int i_ = 0; i_ < 6; i_++) \
        *reinterpret_cast<float4*>(&dst[vkk[i_] * 196 + vj[i_] * 4]) = pv[i_]; }

    unsigned long long acc3[4][3];
#pragma unroll
    for (int i = 0; i < 4; i++) { acc3[i][0] = 0ull; acc3[i][1] = 0ull; acc3[i][2] = 0ull; }

    V_LOAD(0); V_STORE(0); __syncthreads();

    for (int t = 0; t < 32; t++) {
        int buf = t & 1;
        if (t < 31) V_LOAD(t + 1);
        int k0 = t * 32;
        const float* vt = sV + buf * 6272;
#pragma unroll
        for (int kk = 0; kk < 32; kk++) {
            const unsigned long long* br = reinterpret_cast<const unsigned long long*>(vt + kk * 196);
            unsigned long long b0 = br[tn3], b1 = br[tn3 + 1], b2 = br[tn3 + 2];
#pragma unroll
            for (int i = 0; i < 4; i++) {
                float a = sS[(tm + i) * 1024 + k0 + kk];
                unsigned long long ap = pack2(a, a);
                ffma2(acc3[i][0], ap, b0);
                ffma2(acc3[i][1], ap, b1);
                ffma2(acc3[i][2], ap, b2);
            }
        }
        __syncthreads();
        if (t < 31) { V_STORE(buf ^ 1); __syncthreads(); }
    }

    // ---- phase 4: fused LayerNorm (warp-local per row) + write ----
    {
        float gm[6], bt[6];
#pragma unroll
        for (int e = 0; e < 6; e++) { gm[e] = gamma[lane * 6 + e]; bt[e] = beta[lane * 6 + e]; }
#pragma unroll
        for (int i = 0; i < 4; i++) {
            float2 f0 = unpack2(acc3[i][0]), f1 = unpack2(acc3[i][1]), f2 = unpack2(acc3[i][2]);
            float f[6] = {f0.x, f0.y, f1.x, f1.y, f2.x, f2.y};
            float s = 0.f, s2 = 0.f;
#pragma unroll
            for (int e = 0; e < 6; e++) { s += f[e]; s2 += f[e] * f[e]; }
#pragma unroll
            for (int o = 16; o; o >>= 1) {
                s  += __shfl_xor_sync(0xffffffffu, s, o);
                s2 += __shfl_xor_sync(0xffffffffu, s2, o);
            }
            float mean = s * (1.f / 192.f);
            float var  = s2 * (1.f / 192.f) - mean * mean;
            float rstd = rsqrtf(var + 1e-5f);
            float* orow = Oout + (size_t)(b * SEQ + m0 + tm + i) * DQK + lane * 6;
            float2 w0 = make_float2((f[0] - mean) * rstd * gm[0] + bt[0],
                                    (f[1] - mean) * rstd * gm[1] + bt[1]);
            float2 w1 = make_float2((f[2] - mean) * rstd * gm[2] + bt[2],
                                    (f[3] - mean) * rstd * gm[3] + bt[3]);
            float2 w2 = make_float2((f[4] - mean) * rstd * gm[4] + bt[4],
                                    (f[5] - mean) * rstd * gm[5] + bt[5]);
            *reinterpret_cast<float2*>(&orow[0]) = w0;
            *reinterpret_cast<float2*>(&orow[2]) = w1;
            *reinterpret_cast<float2*>(&orow[4]) = w2;
        }
    }
}

// ---------------- launch ----------------
extern "C" void kernel_launch(void* const* d_in, const int* in_sizes, int n_in,
                              void* d_out, int out_size) {
    const float* x     = (const float*)d_in[0];
    const float* w     = (const float*)d_in[1];
    const float* ew    = (const float*)d_in[2];
    const float* tw    = (const float*)d_in[3];
    const float* gamma = (const float*)d_in[4];
    const float* beta  = (const float*)d_in[5];
    (void)in_sizes; (void)n_in; (void)out_size;

    float* out      = (float*)d_out;
    float* out_o    = out;                                  // [16,1024,192]
    float* out_attn = out + (size_t)NTOK * DQK;             // [16,1024,1024]

    static int smem_set = 0;
    if (!smem_set) {
        cudaFuncSetAttribute(fused_attn_kernel,
                             cudaFuncAttributeMaxDynamicSharedMemorySize, FUSED_SMEM);
        smem_set = 1;
    }

    build_U_kernel<<<48, 16>>>(w, ew, tw);
    qkv_kernel<<<dim3(16, NTOK / 128), 128>>>(x);
    fused_attn_kernel<<<dim3(SEQ / 32, 16), 256, FUSED_SMEM>>>(out_attn, out_o, gamma, beta);
}

// round 4
// speedup vs baseline: 1.4942x; 1.4942x over previous
#include <cuda_runtime.h>
#include <math.h>

// Problem dims
#define NTOK 16384          // B*S = 16*1024
#define DQK  192            // 3*F
#define SEQ  1024

// ---------------- device scratch (allocation-free) ----------------
__device__ float  g_q[NTOK * DQK];
__device__ float  g_k[NTOK * DQK];
__device__ float  g_v[NTOK * DQK];
__device__ float2 g_U[48][16][16];   // [qkv*16+split][row][col]

// ---------------- f32x2 packed helpers ----------------
__device__ __forceinline__ unsigned long long pack2(float lo, float hi) {
    unsigned long long r;
    asm("mov.b64 %0, {%1,%2};" : "=l"(r) : "f"(lo), "f"(hi));
    return r;
}
__device__ __forceinline__ void ffma2(unsigned long long& d, unsigned long long a, unsigned long long b) {
    asm("fma.rn.f32x2 %0, %1, %2, %0;" : "+l"(d) : "l"(a), "l"(b));
}
__device__ __forceinline__ float2 unpack2(unsigned long long v) {
    float2 r;
    asm("mov.b64 {%0,%1}, %2;" : "=f"(r.x), "=f"(r.y) : "l"(v));
    return r;
}

// ---------------- complex gate helpers (register state) ----------------
__device__ __forceinline__ void gate_rx(float2* v, int w, float ch, float sh) {
    int bit = 8 >> w;
#pragma unroll
    for (int n = 0; n < 16; n++) if (!(n & bit)) {
        float2 a = v[n], b = v[n | bit];
        v[n]       = make_float2(ch * a.x + sh * b.y, ch * a.y - sh * b.x);
        v[n | bit] = make_float2(ch * b.x + sh * a.y, ch * b.y - sh * a.x);
    }
}
__device__ __forceinline__ void gate_ry(float2* v, int w, float ch, float sh) {
    int bit = 8 >> w;
#pragma unroll
    for (int n = 0; n < 16; n++) if (!(n & bit)) {
        float2 a = v[n], b = v[n | bit];
        v[n]       = make_float2(ch * a.x - sh * b.x, ch * a.y - sh * b.y);
        v[n | bit] = make_float2(sh * a.x + ch * b.x, sh * a.y + ch * b.y);
    }
}
__device__ __forceinline__ void gate_rz(float2* v, int w, float ch, float sh) {
    int bit = 8 >> w;
#pragma unroll
    for (int n = 0; n < 16; n++) {
        float2 a = v[n];
        if (n & bit) v[n] = make_float2(ch * a.x - sh * a.y, ch * a.y + sh * a.x);
        else         v[n] = make_float2(ch * a.x + sh * a.y, ch * a.y - sh * a.x);
    }
}
__device__ __forceinline__ void gate_h(float2* v, int w) {
    int bit = 8 >> w;
    const float r = 0.70710678118654752440f;
#pragma unroll
    for (int n = 0; n < 16; n++) if (!(n & bit)) {
        float2 a = v[n], b = v[n | bit];
        v[n]       = make_float2(r * (a.x + b.x), r * (a.y + b.y));
        v[n | bit] = make_float2(r * (a.x - b.x), r * (a.y - b.y));
    }
}
__device__ __forceinline__ void gate_crx(float2* v, int c, int g, float ch, float sh) {
    int bc = 8 >> c, bg = 8 >> g;
#pragma unroll
    for (int n = 0; n < 16; n++) if ((n & bc) && !(n & bg)) {
        float2 a = v[n], b = v[n | bg];
        v[n]      = make_float2(ch * a.x + sh * b.y, ch * a.y - sh * b.x);
        v[n | bg] = make_float2(ch * b.x + sh * a.y, ch * b.y - sh * a.x);
    }
}
__device__ __forceinline__ void gate_cphase_cs(float2* v, int j, int i, float cp, float sp) {
    int bj = 8 >> j, bi = 8 >> i;
#pragma unroll
    for (int n = 0; n < 16; n++) if ((n & bj) && (n & bi)) {
        float2 a = v[n];
        v[n] = make_float2(cp * a.x - sp * a.y, cp * a.y + sp * a.x);
    }
}
__device__ __forceinline__ void gate_iswap(float2* v, int w0, int w1) {
    int b0 = 8 >> w0, b1 = 8 >> w1;
#pragma unroll
    for (int n = 0; n < 16; n++) if (!(n & b0) && (n & b1)) {
        int m = (n | b0) & ~b1;
        float2 a = v[n], b = v[m];
        v[n] = make_float2(-b.y, b.x);
        v[m] = make_float2(-a.y, a.x);
    }
}
__device__ __forceinline__ void gate_swap(float2* v, int w0, int w1) {
    int b0 = 8 >> w0, b1 = 8 >> w1;
#pragma unroll
    for (int n = 0; n < 16; n++) if (!(n & b0) && (n & b1)) {
        int m = (n | b0) & ~b1;
        float2 t = v[n]; v[n] = v[m]; v[m] = t;
    }
}

// cphase constants: cos/sin of pi/2, pi/4, pi/8
#define CP1 0.0f
#define SP1 1.0f
#define CP2 0.70710678118654752440f
#define SP2 0.70710678118654752440f
#define CP3 0.92387953251128675613f
#define SP3 0.38268343236508977173f

// ---------------- Kernel A: build 48 fixed 16x16 unitaries ----------------
__global__ void __launch_bounds__(16) build_U_kernel(const float* __restrict__ W,
                                                     const float* __restrict__ EW,
                                                     const float* __restrict__ TW) {
    const int u   = blockIdx.x;
    const int col = threadIdx.x;
    const float* w  = W  + u * 12;
    const float* ew = EW + u * 12;
    const float* tw = TW + u * 12;

    float2 v[16];
#pragma unroll
    for (int n = 0; n < 16; n++) v[n] = make_float2(n == col ? 1.f : 0.f, 0.f);

#pragma unroll
    for (int L = 0; L < 3; L++) {
#pragma unroll
        for (int i = 0; i < 4; i++) {
            float sh, ch;
            __sincosf(0.5f * w[L * 4 + i], &sh, &ch);
            gate_rx(v, i, ch, sh);
            gate_ry(v, i, ch, sh);
            gate_rz(v, i, ch, sh);
        }
#pragma unroll
        for (int i = 0; i < 4; i++) {
            float sh, ch;
            __sincosf(0.5f * ew[L * 4 + i], &sh, &ch);
            gate_crx(v, i, (i + 2) & 3, ch, sh);
            gate_crx(v, i, (i + 3) & 3, ch, sh);
        }
        gate_iswap(v, 0, 1); gate_iswap(v, 1, 2); gate_iswap(v, 2, 3); gate_iswap(v, 3, 0);
        { float2 t = v[12]; v[12] = v[14]; v[14] = t;
          t = v[13]; v[13] = v[15]; v[15] = t; }
#pragma unroll
        for (int i = 0; i < 3; i++) {
            float sh, ch;
            __sincosf(0.5f * tw[L * 4 + i], &sh, &ch);
            gate_crx(v, i, i + 1, ch, sh);
        }
        { float sh, ch; __sincosf(0.5f * tw[L * 4 + 3], &sh, &ch); gate_crx(v, 3, 0, ch, sh); }
        // QPE forward
#pragma unroll
        for (int i = 0; i < 4; i++) gate_h(v, i);
        gate_cphase_cs(v, 0, 1, CP1, SP1);
        gate_cphase_cs(v, 0, 2, CP2, SP2); gate_cphase_cs(v, 1, 2, CP1, SP1);
        gate_cphase_cs(v, 0, 3, CP3, SP3); gate_cphase_cs(v, 1, 3, CP2, SP2); gate_cphase_cs(v, 2, 3, CP1, SP1);
        gate_swap(v, 0, 3); gate_swap(v, 1, 2);
        // inverse pass
        gate_h(v, 0);
        gate_h(v, 1); gate_cphase_cs(v, 0, 1, CP1, -SP1);
        gate_h(v, 2); gate_cphase_cs(v, 0, 2, CP2, -SP2); gate_cphase_cs(v, 1, 2, CP1, -SP1);
        gate_h(v, 3); gate_cphase_cs(v, 0, 3, CP3, -SP3); gate_cphase_cs(v, 1, 3, CP2, -SP2); gate_cphase_cs(v, 2, 3, CP1, -SP1);
    }

#pragma unroll
    for (int n = 0; n < 16; n++) g_U[u][n][col] = v[n];
}

// ---------------- Kernel B: per-token QKV via packed 16x16 complex matvec ----------------
__global__ void __launch_bounds__(128) qkv_kernel(const float* __restrict__ x) {
    const int sp  = blockIdx.x;
    const int t0  = blockIdx.y * 128;
    const int tid = threadIdx.x;
    const int t   = t0 + tid;

    __shared__ unsigned long long sUp[3][16][16];
    __shared__ unsigned long long sUm[3][16][16];
    __shared__ float so[128][13];

    for (int r0 = tid; r0 < 768; r0 += 128) {
        int q = r0 >> 8, rem = r0 & 255;
        float2 Uv = g_U[q * 16 + sp][rem >> 4][rem & 15];
        sUp[q][rem >> 4][rem & 15] = pack2(Uv.x, Uv.x);
        sUm[q][rem >> 4][rem & 15] = pack2(-Uv.y, Uv.y);
    }
    __syncthreads();

    const float4 xv = reinterpret_cast<const float4*>(x)[(size_t)t * 16 + sp];
    float cs[4], sn[4];
    __sincosf(0.5f * xv.x, &sn[0], &cs[0]);
    __sincosf(0.5f * xv.y, &sn[1], &cs[1]);
    __sincosf(0.5f * xv.z, &sn[2], &cs[2]);
    __sincosf(0.5f * xv.w, &sn[3], &cs[3]);

    unsigned long long ep[16], er[16];
#pragma unroll
    for (int n = 0; n < 16; n++) {
        float m = (n & 8 ? sn[0] : cs[0]) * (n & 4 ? sn[1] : cs[1]) *
                  (n & 2 ? sn[2] : cs[2]) * (n & 1 ? sn[3] : cs[3]);
        int pc = __popc(n) & 3;
        float ex = (pc == 0) ? m : (pc == 2) ? -m : 0.f;
        float ey = (pc == 1) ? -m : (pc == 3) ? m : 0.f;
        ep[n] = pack2(ex, ey);
        er[n] = pack2(ey, ex);
    }

#pragma unroll
    for (int q = 0; q < 3; q++) {
        float2 psi[16];
#pragma unroll
        for (int r = 0; r < 16; r++) {
            unsigned long long acc = pack2(0.f, 0.f);
#pragma unroll
            for (int k = 0; k < 16; k++) {
                ffma2(acc, sUp[q][r][k], ep[k]);
                ffma2(acc, sUm[q][r][k], er[k]);
            }
            psi[r] = unpack2(acc);
        }
        float o[12];
#pragma unroll
        for (int w = 0; w < 4; w++) {
            int bit = 8 >> w;
            float z = 0.f, xr = 0.f, yi = 0.f;
#pragma unroll
            for (int n = 0; n < 16; n++) {
                if (n & bit) continue;
                float2 a = psi[n], b = psi[n | bit];
                z  += (a.x * a.x + a.y * a.y) - (b.x * b.x + b.y * b.y);
                xr += a.x * b.x + a.y * b.y;
                yi += a.x * b.y - a.y * b.x;
            }
            o[w] = z; o[4 + w] = 2.f * xr; o[8 + w] = 2.f * yi;
        }
        __syncthreads();
#pragma unroll
        for (int m = 0; m < 12; m++) so[tid][m] = o[m];
        __syncthreads();
        float* base = (q == 0 ? g_q : (q == 1 ? g_k : g_v)) + (size_t)t0 * DQK + sp * 12;
        for (int idx = tid; idx < 1536; idx += 128) {
            int row = idx / 12, col = idx - row * 12;
            base[(size_t)row * DQK + col] = so[row][col];
        }
    }
}

// ---------------- Kernel C1: scores = Q K^T / 2 (128x128 tile, f32x2, dup-A) ----------------
__global__ void __launch_bounds__(256) scores_kernel(float* __restrict__ S) {
    const int b  = blockIdx.z;
    const int m0 = blockIdx.y * 128, n0 = blockIdx.x * 128;
    const float* Q = g_q + (size_t)b * SEQ * DQK;
    const float* K = g_k + (size_t)b * SEQ * DQK;

    __shared__ __align__(16) unsigned long long sA2[16][128];  // (q,q) pairs [k][m]
    __shared__ __align__(16) float sB[16][132];                // [k][n]

    const int tid = threadIdx.x;
    const int row = tid & 127;
    const int kq  = tid >> 7;                 // 0..1
    const int am  = (tid >> 4) << 2;          // 0..60 (ULL index / float index)
    const int tn2 = (tid & 15) << 1;          // ULL index (floats 4*(tid&15))

    unsigned long long acc[8][4];
#pragma unroll
    for (int i = 0; i < 8; i++)
#pragma unroll
        for (int j = 0; j < 4; j++) acc[i][j] = pack2(0.f, 0.f);

    float4 pq0, pq1, pk0, pk1;
    const size_t qrow = (size_t)(m0 + row) * DQK;
    const size_t krow = (size_t)(n0 + row) * DQK;

#define SC_LOAD(kc) { int k0 = (kc) * 16; \
    pq0 = *reinterpret_cast<const float4*>(&Q[qrow + k0 + kq * 4]); \
    pq1 = *reinterpret_cast<const float4*>(&Q[qrow + k0 + (kq + 2) * 4]); \
    pk0 = *reinterpret_cast<const float4*>(&K[krow + k0 + kq * 4]); \
    pk1 = *reinterpret_cast<const float4*>(&K[krow + k0 + (kq + 2) * 4]); }

#define SC_STORE() { int c0 = kq * 4, c1 = (kq + 2) * 4; \
    sA2[c0 + 0][row] = pack2(pq0.x, pq0.x); sA2[c0 + 1][row] = pack2(pq0.y, pq0.y); \
    sA2[c0 + 2][row] = pack2(pq0.z, pq0.z); sA2[c0 + 3][row] = pack2(pq0.w, pq0.w); \
    sA2[c1 + 0][row] = pack2(pq1.x, pq1.x); sA2[c1 + 1][row] = pack2(pq1.y, pq1.y); \
    sA2[c1 + 2][row] = pack2(pq1.z, pq1.z); sA2[c1 + 3][row] = pack2(pq1.w, pq1.w); \
    sB[c0 + 0][row] = pk0.x; sB[c0 + 1][row] = pk0.y; sB[c0 + 2][row] = pk0.z; sB[c0 + 3][row] = pk0.w; \
    sB[c1 + 0][row] = pk1.x; sB[c1 + 1][row] = pk1.y; sB[c1 + 2][row] = pk1.z; sB[c1 + 3][row] = pk1.w; }

    SC_LOAD(0); SC_STORE(); __syncthreads();

    for (int kc = 0; kc < 12; kc++) {
        if (kc < 11) SC_LOAD(kc + 1);
#pragma unroll
        for (int kk = 0; kk < 16; kk++) {
            const unsigned long long* aq = &sA2[kk][0];
            ulonglong2 aA0 = *reinterpret_cast<const ulonglong2*>(aq + am);
            ulonglong2 aA1 = *reinterpret_cast<const ulonglong2*>(aq + am + 2);
            ulonglong2 aB0 = *reinterpret_cast<const ulonglong2*>(aq + 64 + am);
            ulonglong2 aB1 = *reinterpret_cast<const ulonglong2*>(aq + 64 + am + 2);
            const unsigned long long* br = reinterpret_cast<const unsigned long long*>(&sB[kk][0]);
            ulonglong2 bb0 = *reinterpret_cast<const ulonglong2*>(br + tn2);
            ulonglong2 bb1 = *reinterpret_cast<const ulonglong2*>(br + 32 + tn2);
            unsigned long long a[8] = {aA0.x, aA0.y, aA1.x, aA1.y, aB0.x, aB0.y, aB1.x, aB1.y};
#pragma unroll
            for (int i = 0; i < 8; i++) {
                ffma2(acc[i][0], a[i], bb0.x);
                ffma2(acc[i][1], a[i], bb0.y);
                ffma2(acc[i][2], a[i], bb1.x);
                ffma2(acc[i][3], a[i], bb1.y);
            }
        }
        __syncthreads();
        if (kc < 11) { SC_STORE(); __syncthreads(); }
    }

    float* Sp = S + ((size_t)b << 20);
    const int tn4 = (tid & 15) << 2;
#pragma unroll
    for (int i = 0; i < 8; i++) {
        int mi = m0 + ((i < 4) ? (am + i) : (64 + am + i - 4));
        float2 p0 = unpack2(acc[i][0]), p1 = unpack2(acc[i][1]);
        float2 p2 = unpack2(acc[i][2]), p3 = unpack2(acc[i][3]);
        float* rowp = Sp + (size_t)mi * SEQ + n0;
        *reinterpret_cast<float4*>(&rowp[tn4])      = make_float4(0.5f * p0.x, 0.5f * p0.y, 0.5f * p1.x, 0.5f * p1.y);
        *reinterpret_cast<float4*>(&rowp[64 + tn4]) = make_float4(0.5f * p2.x, 0.5f * p2.y, 0.5f * p3.x, 0.5f * p3.y);
    }
}

// ---------------- Kernel C2: in-place row softmax over 1024 ----------------
__global__ void __launch_bounds__(256) softmax_kernel(float* __restrict__ A) {
    const int row = blockIdx.x;
    float* p = A + (size_t)row * SEQ;
    const int t = threadIdx.x;

    float4 v = *reinterpret_cast<float4*>(p + t * 4);
    float mx = fmaxf(fmaxf(v.x, v.y), fmaxf(v.z, v.w));
#pragma unroll
    for (int o = 16; o; o >>= 1) mx = fmaxf(mx, __shfl_xor_sync(0xffffffffu, mx, o));

    __shared__ float red[8];
    __shared__ float bmax, bsum;
    if ((t & 31) == 0) red[t >> 5] = mx;
    __syncthreads();
    if (t < 8) {
        float m = red[t];
#pragma unroll
        for (int o = 4; o; o >>= 1) m = fmaxf(m, __shfl_xor_sync(0xffu, m, o));
        if (t == 0) bmax = m;
    }
    __syncthreads();
    const float M = bmax;

    float e0 = expf(v.x - M), e1 = expf(v.y - M), e2 = expf(v.z - M), e3 = expf(v.w - M);
    float s = e0 + e1 + e2 + e3;
#pragma unroll
    for (int o = 16; o; o >>= 1) s += __shfl_xor_sync(0xffffffffu, s, o);
    if ((t & 31) == 0) red[t >> 5] = s;
    __syncthreads();
    if (t < 8) {
        float m = red[t];
#pragma unroll
        for (int o = 4; o; o >>= 1) m += __shfl_xor_sync(0xffu, m, o);
        if (t == 0) bsum = m;
    }
    __syncthreads();
    const float inv = 1.f / bsum;
    *reinterpret_cast<float4*>(p + t * 4) = make_float4(e0 * inv, e1 * inv, e2 * inv, e3 * inv);
}

// ---------------- Kernel C3: O = A @ V (128x192 tile, f32x2, dup-A) ----------------
__global__ void __launch_bounds__(256) o_kernel(const float* __restrict__ A, float* __restrict__ O) {
    const int b  = blockIdx.z;
    const int m0 = blockIdx.y * 128;
    const float* Ab = A + ((size_t)b << 20);
    const float* V  = g_v + (size_t)b * SEQ * DQK;

    __shared__ __align__(16) unsigned long long sA2[16][128];  // (a,a) pairs [k][m]
    __shared__ __align__(16) float sV[16][196];                // [k][n]

    const int tid = threadIdx.x;
    const int row = tid & 127;
    const int kq  = tid >> 7;
    const int am  = (tid >> 4) << 2;
    const int tn3 = (tid & 15) * 6;      // ULL idx (floats 12*(tid&15))? no: lane n mapping below

    // n mapping: 16 groups × 12 floats = 192; group g covers floats 12g..12g+11 → 6 ULL
    unsigned long long acc[8][6];
#pragma unroll
    for (int i = 0; i < 8; i++)
#pragma unroll
        for (int j = 0; j < 6; j++) acc[i][j] = pack2(0.f, 0.f);

    float4 pa0, pa1, pv0, pv1, pv2;
    const size_t arow = (size_t)(m0 + row) * SEQ;
    int vkk[3], vj[3];
#pragma unroll
    for (int r = 0; r < 3; r++) {
        int f = r * 256 + tid;
        vj[r] = f % 48; vkk[r] = f / 48;
    }

#define O_LOAD(kc) { int k0 = (kc) * 16; \
    pa0 = *reinterpret_cast<const float4*>(&Ab[arow + k0 + kq * 4]); \
    pa1 = *reinterpret_cast<const float4*>(&Ab[arow + k0 + (kq + 2) * 4]); \
    pv0 = *reinterpret_cast<const float4*>(&V[(size_t)(k0 + vkk[0]) * DQK + vj[0] * 4]); \
    pv1 = *reinterpret_cast<const float4*>(&V[(size_t)(k0 + vkk[1]) * DQK + vj[1] * 4]); \
    pv2 = *reinterpret_cast<const float4*>(&V[(size_t)(k0 + vkk[2]) * DQK + vj[2] * 4]); }

#define O_STORE() { int c0 = kq * 4, c1 = (kq + 2) * 4; \
    sA2[c0 + 0][row] = pack2(pa0.x, pa0.x); sA2[c0 + 1][row] = pack2(pa0.y, pa0.y); \
    sA2[c0 + 2][row] = pack2(pa0.z, pa0.z); sA2[c0 + 3][row] = pack2(pa0.w, pa0.w); \
    sA2[c1 + 0][row] = pack2(pa1.x, pa1.x); sA2[c1 + 1][row] = pack2(pa1.y, pa1.y); \
    sA2[c1 + 2][row] = pack2(pa1.z, pa1.z); sA2[c1 + 3][row] = pack2(pa1.w, pa1.w); \
    *reinterpret_cast<float4*>(&sV[vkk[0]][vj[0] * 4]) = pv0; \
    *reinterpret_cast<float4*>(&sV[vkk[1]][vj[1] * 4]) = pv1; \
    *reinterpret_cast<float4*>(&sV[vkk[2]][vj[2] * 4]) = pv2; }

    O_LOAD(0); O_STORE(); __syncthreads();

    for (int t = 0; t < 64; t++) {
        if (t < 63) O_LOAD(t + 1);
#pragma unroll
        for (int kk = 0; kk < 16; kk++) {
            const unsigned long long* aq = &sA2[kk][0];
            ulonglong2 aA0 = *reinterpret_cast<const ulonglong2*>(aq + am);
            ulonglong2 aA1 = *reinterpret_cast<const ulonglong2*>(aq + am + 2);
            ulonglong2 aB0 = *reinterpret_cast<const ulonglong2*>(aq + 64 + am);
            ulonglong2 aB1 = *reinterpret_cast<const ulonglong2*>(aq + 64 + am + 2);
            const unsigned long long* br = reinterpret_cast<const unsigned long long*>(&sV[kk][0]);
            unsigned long long b0 = br[tn3], b1 = br[tn3 + 1], b2 = br[tn3 + 2];
            unsigned long long b3 = br[tn3 + 3], b4 = br[tn3 + 4], b5 = br[tn3 + 5];
            unsigned long long a[8] = {aA0.x, aA0.y, aA1.x, aA1.y, aB0.x, aB0.y, aB1.x, aB1.y};
#pragma unroll
            for (int i = 0; i < 8; i++) {
                ffma2(acc[i][0], a[i], b0);
                ffma2(acc[i][1], a[i], b1);
                ffma2(acc[i][2], a[i], b2);
                ffma2(acc[i][3], a[i], b3);
                ffma2(acc[i][4], a[i], b4);
                ffma2(acc[i][5], a[i], b5);
            }
        }
        __syncthreads();
        if (t < 63) { O_STORE(); __syncthreads(); }
    }

    float* Ob = O + (size_t)b * SEQ * DQK;
    const int nf = (tid & 15) * 12;      // first output float column
#pragma unroll
    for (int i = 0; i < 8; i++) {
        int mi = m0 + ((i < 4) ? (am + i) : (64 + am + i - 4));
        float* rowp = Ob + (size_t)mi * DQK + nf;
        float2 p0 = unpack2(acc[i][0]), p1 = unpack2(acc[i][1]), p2 = unpack2(acc[i][2]);
        float2 p3 = unpack2(acc[i][3]), p4 = unpack2(acc[i][4]), p5 = unpack2(acc[i][5]);
        *reinterpret_cast<float4*>(&rowp[0]) = make_float4(p0.x, p0.y, p1.x, p1.y);
        *reinterpret_cast<float4*>(&rowp[4]) = make_float4(p2.x, p2.y, p3.x, p3.y);
        *reinterpret_cast<float4*>(&rowp[8]) = make_float4(p4.x, p4.y, p5.x, p5.y);
    }
}

// ---------------- Kernel C4: in-place LayerNorm over 192 ----------------
__global__ void __launch_bounds__(192) ln_kernel(float* __restrict__ O,
                                                 const float* __restrict__ gamma,
                                                 const float* __restrict__ beta) {
    const int row = blockIdx.x;
    const int t = threadIdx.x;
    float* p = O + (size_t)row * DQK;
    float v = p[t];
    float s = v, s2 = v * v;
#pragma unroll
    for (int o = 16; o; o >>= 1) {
        s  += __shfl_xor_sync(0xffffffffu, s, o);
        s2 += __shfl_xor_sync(0xffffffffu, s2, o);
    }
    __shared__ float ws[6], ws2[6];
    __shared__ float mb[2];
    if ((t & 31) == 0) { ws[t >> 5] = s; ws2[t >> 5] = s2; }
    __syncthreads();
    if (t == 0) {
        float a = 0.f, b2 = 0.f;
#pragma unroll
        for (int i = 0; i < 6; i++) { a += ws[i]; b2 += ws2[i]; }
        float mean = a * (1.f / 192.f);
        float var  = b2 * (1.f / 192.f) - mean * mean;
        mb[0] = mean;
        mb[1] = rsqrtf(var + 1e-5f);
    }
    __syncthreads();
    p[t] = (v - mb[0]) * mb[1] * gamma[t] + beta[t];
}

// ---------------- launch ----------------
extern "C" void kernel_launch(void* const* d_in, const int* in_sizes, int n_in,
                              void* d_out, int out_size) {
    const float* x     = (const float*)d_in[0];
    const float* w     = (const float*)d_in[1];
    const float* ew    = (const float*)d_in[2];
    const float* tw    = (const float*)d_in[3];
    const float* gamma = (const float*)d_in[4];
    const float* beta  = (const float*)d_in[5];
    (void)in_sizes; (void)n_in; (void)out_size;

    float* out      = (float*)d_out;
    float* out_o    = out;                                  // [16,1024,192]
    float* out_attn = out + (size_t)NTOK * DQK;             // [16,1024,1024]

    build_U_kernel<<<48, 16>>>(w, ew, tw);
    qkv_kernel<<<dim3(16, NTOK / 128), 128>>>(x);
    scores_kernel<<<dim3(8, 8, 16), 256>>>(out_attn);
    softmax_kernel<<<NTOK, 256>>>(out_attn);
    o_kernel<<<dim3(1, 8, 16), 256>>>(out_attn, out_o);
    ln_kernel<<<NTOK, 192>>>(out_o, gamma, beta);
}

// round 5
// speedup vs baseline: 1.8054x; 1.2083x over previous
#include <cuda_runtime.h>
#include <math.h>

// Problem dims
#define NTOK 16384          // B*S = 16*1024
#define DQK  192            // 3*F
#define SEQ  1024

// ---------------- device scratch (allocation-free) ----------------
__device__ float  g_q[NTOK * DQK];
__device__ float  g_k[NTOK * DQK];
__device__ float  g_v[NTOK * DQK];
__device__ float2 g_U[48][16][16];   // [qkv*16+split][row][col]

// ---------------- f32x2 packed helpers ----------------
__device__ __forceinline__ unsigned long long pack2(float lo, float hi) {
    unsigned long long r;
    asm("mov.b64 %0, {%1,%2};" : "=l"(r) : "f"(lo), "f"(hi));
    return r;
}
__device__ __forceinline__ void ffma2(unsigned long long& d, unsigned long long a, unsigned long long b) {
    asm("fma.rn.f32x2 %0, %1, %2, %0;" : "+l"(d) : "l"(a), "l"(b));
}
__device__ __forceinline__ float2 unpack2(unsigned long long v) {
    float2 r;
    asm("mov.b64 {%0,%1}, %2;" : "=f"(r.x), "=f"(r.y) : "l"(v));
    return r;
}

// ---------------- complex gate helpers (register state) ----------------
__device__ __forceinline__ void gate_rx(float2* v, int w, float ch, float sh) {
    int bit = 8 >> w;
#pragma unroll
    for (int n = 0; n < 16; n++) if (!(n & bit)) {
        float2 a = v[n], b = v[n | bit];
        v[n]       = make_float2(ch * a.x + sh * b.y, ch * a.y - sh * b.x);
        v[n | bit] = make_float2(ch * b.x + sh * a.y, ch * b.y - sh * a.x);
    }
}
__device__ __forceinline__ void gate_ry(float2* v, int w, float ch, float sh) {
    int bit = 8 >> w;
#pragma unroll
    for (int n = 0; n < 16; n++) if (!(n & bit)) {
        float2 a = v[n], b = v[n | bit];
        v[n]       = make_float2(ch * a.x - sh * b.x, ch * a.y - sh * b.y);
        v[n | bit] = make_float2(sh * a.x + ch * b.x, sh * a.y + ch * b.y);
    }
}
__device__ __forceinline__ void gate_rz(float2* v, int w, float ch, float sh) {
    int bit = 8 >> w;
#pragma unroll
    for (int n = 0; n < 16; n++) {
        float2 a = v[n];
        if (n & bit) v[n] = make_float2(ch * a.x - sh * a.y, ch * a.y + sh * a.x);
        else         v[n] = make_float2(ch * a.x + sh * a.y, ch * a.y - sh * a.x);
    }
}
__device__ __forceinline__ void gate_h(float2* v, int w) {
    int bit = 8 >> w;
    const float r = 0.70710678118654752440f;
#pragma unroll
    for (int n = 0; n < 16; n++) if (!(n & bit)) {
        float2 a = v[n], b = v[n | bit];
        v[n]       = make_float2(r * (a.x + b.x), r * (a.y + b.y));
        v[n | bit] = make_float2(r * (a.x - b.x), r * (a.y - b.y));
    }
}
__device__ __forceinline__ void gate_crx(float2* v, int c, int g, float ch, float sh) {
    int bc = 8 >> c, bg = 8 >> g;
#pragma unroll
    for (int n = 0; n < 16; n++) if ((n & bc) && !(n & bg)) {
        float2 a = v[n], b = v[n | bg];
        v[n]      = make_float2(ch * a.x + sh * b.y, ch * a.y - sh * b.x);
        v[n | bg] = make_float2(ch * b.x + sh * a.y, ch * b.y - sh * a.x);
    }
}
__device__ __forceinline__ void gate_cphase_cs(float2* v, int j, int i, float cp, float sp) {
    int bj = 8 >> j, bi = 8 >> i;
#pragma unroll
    for (int n = 0; n < 16; n++) if ((n & bj) && (n & bi)) {
        float2 a = v[n];
        v[n] = make_float2(cp * a.x - sp * a.y, cp * a.y + sp * a.x);
    }
}
__device__ __forceinline__ void gate_iswap(float2* v, int w0, int w1) {
    int b0 = 8 >> w0, b1 = 8 >> w1;
#pragma unroll
    for (int n = 0; n < 16; n++) if (!(n & b0) && (n & b1)) {
        int m = (n | b0) & ~b1;
        float2 a = v[n], b = v[m];
        v[n] = make_float2(-b.y, b.x);
        v[m] = make_float2(-a.y, a.x);
    }
}
__device__ __forceinline__ void gate_swap(float2* v, int w0, int w1) {
    int b0 = 8 >> w0, b1 = 8 >> w1;
#pragma unroll
    for (int n = 0; n < 16; n++) if (!(n & b0) && (n & b1)) {
        int m = (n | b0) & ~b1;
        float2 t = v[n]; v[n] = v[m]; v[m] = t;
    }
}

// cphase constants: cos/sin of pi/2, pi/4, pi/8
#define CP1 0.0f
#define SP1 1.0f
#define CP2 0.70710678118654752440f
#define SP2 0.70710678118654752440f
#define CP3 0.92387953251128675613f
#define SP3 0.38268343236508977173f

// ---------------- Kernel A: build 48 fixed 16x16 unitaries ----------------
__global__ void __launch_bounds__(16) build_U_kernel(const float* __restrict__ W,
                                                     const float* __restrict__ EW,
                                                     const float* __restrict__ TW) {
    const int u   = blockIdx.x;
    const int col = threadIdx.x;
    const float* w  = W  + u * 12;
    const float* ew = EW + u * 12;
    const float* tw = TW + u * 12;

    float2 v[16];
#pragma unroll
    for (int n = 0; n < 16; n++) v[n] = make_float2(n == col ? 1.f : 0.f, 0.f);

#pragma unroll
    for (int L = 0; L < 3; L++) {
#pragma unroll
        for (int i = 0; i < 4; i++) {
            float sh, ch;
            __sincosf(0.5f * w[L * 4 + i], &sh, &ch);
            gate_rx(v, i, ch, sh);
            gate_ry(v, i, ch, sh);
            gate_rz(v, i, ch, sh);
        }
#pragma unroll
        for (int i = 0; i < 4; i++) {
            float sh, ch;
            __sincosf(0.5f * ew[L * 4 + i], &sh, &ch);
            gate_crx(v, i, (i + 2) & 3, ch, sh);
            gate_crx(v, i, (i + 3) & 3, ch, sh);
        }
        gate_iswap(v, 0, 1); gate_iswap(v, 1, 2); gate_iswap(v, 2, 3); gate_iswap(v, 3, 0);
        { float2 t = v[12]; v[12] = v[14]; v[14] = t;
          t = v[13]; v[13] = v[15]; v[15] = t; }
#pragma unroll
        for (int i = 0; i < 3; i++) {
            float sh, ch;
            __sincosf(0.5f * tw[L * 4 + i], &sh, &ch);
            gate_crx(v, i, i + 1, ch, sh);
        }
        { float sh, ch; __sincosf(0.5f * tw[L * 4 + 3], &sh, &ch); gate_crx(v, 3, 0, ch, sh); }
        // QPE forward
#pragma unroll
        for (int i = 0; i < 4; i++) gate_h(v, i);
        gate_cphase_cs(v, 0, 1, CP1, SP1);
        gate_cphase_cs(v, 0, 2, CP2, SP2); gate_cphase_cs(v, 1, 2, CP1, SP1);
        gate_cphase_cs(v, 0, 3, CP3, SP3); gate_cphase_cs(v, 1, 3, CP2, SP2); gate_cphase_cs(v, 2, 3, CP1, SP1);
        gate_swap(v, 0, 3); gate_swap(v, 1, 2);
        // inverse pass
        gate_h(v, 0);
        gate_h(v, 1); gate_cphase_cs(v, 0, 1, CP1, -SP1);
        gate_h(v, 2); gate_cphase_cs(v, 0, 2, CP2, -SP2); gate_cphase_cs(v, 1, 2, CP1, -SP1);
        gate_h(v, 3); gate_cphase_cs(v, 0, 3, CP3, -SP3); gate_cphase_cs(v, 1, 3, CP2, -SP2); gate_cphase_cs(v, 2, 3, CP1, -SP1);
    }

#pragma unroll
    for (int n = 0; n < 16; n++) g_U[u][n][col] = v[n];
}

// ---------------- Kernel B: per-token QKV via packed 16x16 complex matvec ----------------
__global__ void __launch_bounds__(128) qkv_kernel(const float* __restrict__ x) {
    const int sp  = blockIdx.x;
    const int t0  = blockIdx.y * 128;
    const int tid = threadIdx.x;
    const int t   = t0 + tid;

    __shared__ unsigned long long sUp[3][16][16];
    __shared__ unsigned long long sUm[3][16][16];
    __shared__ float so[128][13];

    for (int r0 = tid; r0 < 768; r0 += 128) {
        int q = r0 >> 8, rem = r0 & 255;
        float2 Uv = g_U[q * 16 + sp][rem >> 4][rem & 15];
        sUp[q][rem >> 4][rem & 15] = pack2(Uv.x, Uv.x);
        sUm[q][rem >> 4][rem & 15] = pack2(-Uv.y, Uv.y);
    }
    __syncthreads();

    const float4 xv = reinterpret_cast<const float4*>(x)[(size_t)t * 16 + sp];
    float cs[4], sn[4];
    __sincosf(0.5f * xv.x, &sn[0], &cs[0]);
    __sincosf(0.5f * xv.y, &sn[1], &cs[1]);
    __sincosf(0.5f * xv.z, &sn[2], &cs[2]);
    __sincosf(0.5f * xv.w, &sn[3], &cs[3]);

    unsigned long long ep[16], er[16];
#pragma unroll
    for (int n = 0; n < 16; n++) {
        float m = (n & 8 ? sn[0] : cs[0]) * (n & 4 ? sn[1] : cs[1]) *
                  (n & 2 ? sn[2] : cs[2]) * (n & 1 ? sn[3] : cs[3]);
        int pc = __popc(n) & 3;
        float ex = (pc == 0) ? m : (pc == 2) ? -m : 0.f;
        float ey = (pc == 1) ? -m : (pc == 3) ? m : 0.f;
        ep[n] = pack2(ex, ey);
        er[n] = pack2(ey, ex);
    }

#pragma unroll
    for (int q = 0; q < 3; q++) {
        float2 psi[16];
#pragma unroll
        for (int r = 0; r < 16; r++) {
            unsigned long long acc = pack2(0.f, 0.f);
#pragma unroll
            for (int k = 0; k < 16; k++) {
                ffma2(acc, sUp[q][r][k], ep[k]);
                ffma2(acc, sUm[q][r][k], er[k]);
            }
            psi[r] = unpack2(acc);
        }
        float o[12];
#pragma unroll
        for (int w = 0; w < 4; w++) {
            int bit = 8 >> w;
            float z = 0.f, xr = 0.f, yi = 0.f;
#pragma unroll
            for (int n = 0; n < 16; n++) {
                if (n & bit) continue;
                float2 a = psi[n], b = psi[n | bit];
                z  += (a.x * a.x + a.y * a.y) - (b.x * b.x + b.y * b.y);
                xr += a.x * b.x + a.y * b.y;
                yi += a.x * b.y - a.y * b.x;
            }
            o[w] = z; o[4 + w] = 2.f * xr; o[8 + w] = 2.f * yi;
        }
        __syncthreads();
#pragma unroll
        for (int m = 0; m < 12; m++) so[tid][m] = o[m];
        __syncthreads();
        float* base = (q == 0 ? g_q : (q == 1 ? g_k : g_v)) + (size_t)t0 * DQK + sp * 12;
        for (int idx = tid; idx < 1536; idx += 128) {
            int row = idx / 12, col = idx - row * 12;
            base[(size_t)row * DQK + col] = so[row][col];
        }
    }
}

// ---------------- Kernel C1: scores = Q K^T / 2 (128x128 tile, f32x2) ----------------
__global__ void __launch_bounds__(256) scores_kernel(float* __restrict__ S) {
    const int b  = blockIdx.z;
    const int m0 = blockIdx.y * 128, n0 = blockIdx.x * 128;
    const float* Q = g_q + (size_t)b * SEQ * DQK;
    const float* K = g_k + (size_t)b * SEQ * DQK;

    __shared__ __align__(16) float sA[16][128];   // [k][m]
    __shared__ __align__(16) float sB[16][128];   // [k][n]

    const int tid = threadIdx.x;
    const int row = tid & 127;
    const int kq  = tid >> 7;                 // 0..1
    const int am  = (tid >> 4) << 2;          // 0..60
    const int tn4 = (tid & 15) << 2;          // 0..60

    unsigned long long acc[8][4];
#pragma unroll
    for (int i = 0; i < 8; i++)
#pragma unroll
        for (int j = 0; j < 4; j++) acc[i][j] = pack2(0.f, 0.f);

    float4 pq0, pq1, pk0, pk1;
    const size_t qrow = (size_t)(m0 + row) * DQK;
    const size_t krow = (size_t)(n0 + row) * DQK;

#define SC_LOAD(kc) { int k0 = (kc) * 16; \
    pq0 = *reinterpret_cast<const float4*>(&Q[qrow + k0 + kq * 4]); \
    pq1 = *reinterpret_cast<const float4*>(&Q[qrow + k0 + (kq + 2) * 4]); \
    pk0 = *reinterpret_cast<const float4*>(&K[krow + k0 + kq * 4]); \
    pk1 = *reinterpret_cast<const float4*>(&K[krow + k0 + (kq + 2) * 4]); }

#define SC_STORE() { int c0 = kq * 4, c1 = (kq + 2) * 4; \
    sA[c0 + 0][row] = pq0.x; sA[c0 + 1][row] = pq0.y; sA[c0 + 2][row] = pq0.z; sA[c0 + 3][row] = pq0.w; \
    sA[c1 + 0][row] = pq1.x; sA[c1 + 1][row] = pq1.y; sA[c1 + 2][row] = pq1.z; sA[c1 + 3][row] = pq1.w; \
    sB[c0 + 0][row] = pk0.x; sB[c0 + 1][row] = pk0.y; sB[c0 + 2][row] = pk0.z; sB[c0 + 3][row] = pk0.w; \
    sB[c1 + 0][row] = pk1.x; sB[c1 + 1][row] = pk1.y; sB[c1 + 2][row] = pk1.z; sB[c1 + 3][row] = pk1.w; }

    SC_LOAD(0); SC_STORE(); __syncthreads();

    for (int kc = 0; kc < 12; kc++) {
        if (kc < 11) SC_LOAD(kc + 1);
#pragma unroll
        for (int kk = 0; kk < 16; kk++) {
            float4 a0 = *reinterpret_cast<const float4*>(&sA[kk][am]);
            float4 a1 = *reinterpret_cast<const float4*>(&sA[kk][64 + am]);
            const unsigned long long* br = reinterpret_cast<const unsigned long long*>(&sB[kk][0]);
            unsigned long long b0 = br[tn4 >> 1], b1 = br[(tn4 >> 1) + 1];
            unsigned long long b2 = br[(64 + tn4) >> 1], b3 = br[((64 + tn4) >> 1) + 1];
            float av[8] = {a0.x, a0.y, a0.z, a0.w, a1.x, a1.y, a1.z, a1.w};
#pragma unroll
            for (int i = 0; i < 8; i++) {
                unsigned long long ap = pack2(av[i], av[i]);
                ffma2(acc[i][0], ap, b0);
                ffma2(acc[i][1], ap, b1);
                ffma2(acc[i][2], ap, b2);
                ffma2(acc[i][3], ap, b3);
            }
        }
        __syncthreads();
        if (kc < 11) { SC_STORE(); __syncthreads(); }
    }

    float* Sp = S + ((size_t)b << 20);
#pragma unroll
    for (int i = 0; i < 8; i++) {
        int mi = m0 + ((i < 4) ? (am + i) : (64 + am + i - 4));
        float2 p0 = unpack2(acc[i][0]), p1 = unpack2(acc[i][1]);
        float2 p2 = unpack2(acc[i][2]), p3 = unpack2(acc[i][3]);
        float* rowp = Sp + (size_t)mi * SEQ + n0;
        *reinterpret_cast<float4*>(&rowp[tn4])      = make_float4(0.5f * p0.x, 0.5f * p0.y, 0.5f * p1.x, 0.5f * p1.y);
        *reinterpret_cast<float4*>(&rowp[64 + tn4]) = make_float4(0.5f * p2.x, 0.5f * p2.y, 0.5f * p3.x, 0.5f * p3.y);
    }
}

// ---------------- Kernel C2: in-place row softmax over 1024 ----------------
__global__ void __launch_bounds__(256) softmax_kernel(float* __restrict__ A) {
    const int row = blockIdx.x;
    float* p = A + (size_t)row * SEQ;
    const int t = threadIdx.x;

    float4 v = *reinterpret_cast<float4*>(p + t * 4);
    float mx = fmaxf(fmaxf(v.x, v.y), fmaxf(v.z, v.w));
#pragma unroll
    for (int o = 16; o; o >>= 1) mx = fmaxf(mx, __shfl_xor_sync(0xffffffffu, mx, o));

    __shared__ float red[8];
    __shared__ float bmax, bsum;
    if ((t & 31) == 0) red[t >> 5] = mx;
    __syncthreads();
    if (t < 8) {
        float m = red[t];
#pragma unroll
        for (int o = 4; o; o >>= 1) m = fmaxf(m, __shfl_xor_sync(0xffu, m, o));
        if (t == 0) bmax = m;
    }
    __syncthreads();
    const float M = bmax;

    float e0 = expf(v.x - M), e1 = expf(v.y - M), e2 = expf(v.z - M), e3 = expf(v.w - M);
    float s = e0 + e1 + e2 + e3;
#pragma unroll
    for (int o = 16; o; o >>= 1) s += __shfl_xor_sync(0xffffffffu, s, o);
    if ((t & 31) == 0) red[t >> 5] = s;
    __syncthreads();
    if (t < 8) {
        float m = red[t];
#pragma unroll
        for (int o = 4; o; o >>= 1) m += __shfl_xor_sync(0xffu, m, o);
        if (t == 0) bsum = m;
    }
    __syncthreads();
    const float inv = 1.f / bsum;
    *reinterpret_cast<float4*>(p + t * 4) = make_float4(e0 * inv, e1 * inv, e2 * inv, e3 * inv);
}

// ---------------- Kernel C3: O = A @ V (128x192 tile) + fused LayerNorm ----------------
__global__ void __launch_bounds__(256) o_kernel(const float* __restrict__ A, float* __restrict__ O,
                                                const float* __restrict__ gamma,
                                                const float* __restrict__ beta) {
    const int b  = blockIdx.z;
    const int m0 = blockIdx.y * 128;
    const float* Ab = A + ((size_t)b << 20);
    const float* V  = g_v + (size_t)b * SEQ * DQK;

    __shared__ __align__(16) float sA[16][128];   // [k][m]
    __shared__ __align__(16) float sV[16][192];   // [k][n]

    const int tid = threadIdx.x;
    const int row = tid & 127;
    const int kq  = tid >> 7;
    const int am  = (tid >> 4) << 2;
    const int tn4 = (tid & 15) << 2;

    unsigned long long acc[8][6];
#pragma unroll
    for (int i = 0; i < 8; i++)
#pragma unroll
        for (int j = 0; j < 6; j++) acc[i][j] = pack2(0.f, 0.f);

    float4 pa0, pa1, pv0, pv1, pv2;
    const size_t arow = (size_t)(m0 + row) * SEQ;
    int vnq[3], vkk[3];
#pragma unroll
    for (int r = 0; r < 3; r++) {
        int f = r * 256 + tid;
        vnq[r] = f % 48; vkk[r] = f / 48;
    }

#define O_LOAD(kc) { int k0 = (kc) * 16; \
    pa0 = *reinterpret_cast<const float4*>(&Ab[arow + k0 + kq * 4]); \
    pa1 = *reinterpret_cast<const float4*>(&Ab[arow + k0 + (kq + 2) * 4]); \
    pv0 = *reinterpret_cast<const float4*>(&V[(size_t)(k0 + vkk[0]) * DQK + vnq[0] * 4]); \
    pv1 = *reinterpret_cast<const float4*>(&V[(size_t)(k0 + vkk[1]) * DQK + vnq[1] * 4]); \
    pv2 = *reinterpret_cast<const float4*>(&V[(size_t)(k0 + vkk[2]) * DQK + vnq[2] * 4]); }

#define O_STORE() { int c0 = kq * 4, c1 = (kq + 2) * 4; \
    sA[c0 + 0][row] = pa0.x; sA[c0 + 1][row] = pa0.y; sA[c0 + 2][row] = pa0.z; sA[c0 + 3][row] = pa0.w; \
    sA[c1 + 0][row] = pa1.x; sA[c1 + 1][row] = pa1.y; sA[c1 + 2][row] = pa1.z; sA[c1 + 3][row] = pa1.w; \
    reinterpret_cast<float4*>(&sV[vkk[0]][0])[vnq[0]] = pv0; \
    reinterpret_cast<float4*>(&sV[vkk[1]][0])[vnq[1]] = pv1; \
    reinterpret_cast<float4*>(&sV[vkk[2]][0])[vnq[2]] = pv2; }

    O_LOAD(0); O_STORE(); __syncthreads();

    for (int kc = 0; kc < 64; kc++) {
        if (kc < 63) O_LOAD(kc + 1);
#pragma unroll
        for (int kk = 0; kk < 16; kk++) {
            float4 a0 = *reinterpret_cast<const float4*>(&sA[kk][am]);
            float4 a1 = *reinterpret_cast<const float4*>(&sA[kk][64 + am]);
            const unsigned long long* br = reinterpret_cast<const unsigned long long*>(&sV[kk][0]);
            unsigned long long b0 = br[tn4 >> 1],         b1 = br[(tn4 >> 1) + 1];
            unsigned long long b2 = br[(64 + tn4) >> 1],  b3 = br[((64 + tn4) >> 1) + 1];
            unsigned long long b4 = br[(128 + tn4) >> 1], b5 = br[((128 + tn4) >> 1) + 1];
            float av[8] = {a0.x, a0.y, a0.z, a0.w, a1.x, a1.y, a1.z, a1.w};
#pragma unroll
            for (int i = 0; i < 8; i++) {
                unsigned long long ap = pack2(av[i], av[i]);
                ffma2(acc[i][0], ap, b0);
                ffma2(acc[i][1], ap, b1);
                ffma2(acc[i][2], ap, b2);
                ffma2(acc[i][3], ap, b3);
                ffma2(acc[i][4], ap, b4);
                ffma2(acc[i][5], ap, b5);
            }
        }
        __syncthreads();
        if (kc < 63) { O_STORE(); __syncthreads(); }
    }

    // ---- fused LayerNorm epilogue ----
    // Row mi's 192 outputs live across the 16 threads sharing (tid>>4):
    // this thread owns cols {tn4..tn4+3, 64+tn4.., 128+tn4..}. Reduce via
    // 16-lane xor shuffles (offsets 1,2,4,8 stay within the half-warp segment).
    float gmv[12], btv[12];
#pragma unroll
    for (int g = 0; g < 3; g++) {
        float4 gg = *reinterpret_cast<const float4*>(&gamma[g * 64 + tn4]);
        float4 bb = *reinterpret_cast<const float4*>(&beta [g * 64 + tn4]);
        gmv[g * 4 + 0] = gg.x; gmv[g * 4 + 1] = gg.y; gmv[g * 4 + 2] = gg.z; gmv[g * 4 + 3] = gg.w;
        btv[g * 4 + 0] = bb.x; btv[g * 4 + 1] = bb.y; btv[g * 4 + 2] = bb.z; btv[g * 4 + 3] = bb.w;
    }

    float* Ob = O + (size_t)b * SEQ * DQK;
#pragma unroll
    for (int i = 0; i < 8; i++) {
        int mi = m0 + ((i < 4) ? (am + i) : (64 + am + i - 4));
        float f[12];
#pragma unroll
        for (int g = 0; g < 6; g++) {
            float2 p = unpack2(acc[i][g]);
            f[g * 2] = p.x; f[g * 2 + 1] = p.y;
        }
        float s = 0.f, s2 = 0.f;
#pragma unroll
        for (int e = 0; e < 12; e++) { s += f[e]; s2 += f[e] * f[e]; }
#pragma unroll
        for (int o = 8; o; o >>= 1) {
            s  += __shfl_xor_sync(0xffffffffu, s, o);
            s2 += __shfl_xor_sync(0xffffffffu, s2, o);
        }
        float mean = s * (1.f / 192.f);
        float var  = s2 * (1.f / 192.f) - mean * mean;
        float rstd = rsqrtf(var + 1e-5f);
        float* rowp = Ob + (size_t)mi * DQK;
#pragma unroll
        for (int g = 0; g < 3; g++) {
            float4 w;
            w.x = (f[g * 4 + 0] - mean) * rstd * gmv[g * 4 + 0] + btv[g * 4 + 0];
            w.y = (f[g * 4 + 1] - mean) * rstd * gmv[g * 4 + 1] + btv[g * 4 + 1];
            w.z = (f[g * 4 + 2] - mean) * rstd * gmv[g * 4 + 2] + btv[g * 4 + 2];
            w.w = (f[g * 4 + 3] - mean) * rstd * gmv[g * 4 + 3] + btv[g * 4 + 3];
            *reinterpret_cast<float4*>(&rowp[g * 64 + tn4]) = w;
        }
    }
}

// ---------------- launch ----------------
extern "C" void kernel_launch(void* const* d_in, const int* in_sizes, int n_in,
                              void* d_out, int out_size) {
    const float* x     = (const float*)d_in[0];
    const float* w     = (const float*)d_in[1];
    const float* ew    = (const float*)d_in[2];
    const float* tw    = (const float*)d_in[3];
    const float* gamma = (const float*)d_in[4];
    const float* beta  = (const float*)d_in[5];
    (void)in_sizes; (void)n_in; (void)out_size;

    float* out      = (float*)d_out;
    float* out_o    = out;                                  // [16,1024,192]
    float* out_attn = out + (size_t)NTOK * DQK;             // [16,1024,1024]

    build_U_kernel<<<48, 16>>>(w, ew, tw);
    qkv_kernel<<<dim3(16, NTOK / 128), 128>>>(x);
    scores_kernel<<<dim3(8, 8, 16), 256>>>(out_attn);
    softmax_kernel<<<NTOK, 256>>>(out_attn);
    o_kernel<<<dim3(1, 8, 16), 256>>>(out_attn, out_o, gamma, beta);
}

// round 7
// speedup vs baseline: 2.4046x; 1.3319x over previous
#include <cuda_runtime.h>
#include <cuda_bf16.h>
#include <mma.h>
#include <math.h>
#include <stdint.h>

using namespace nvcuda;

// Problem dims
#define NTOK 16384          // B*S
#define DQK  192
#define SEQ  1024
#define NB   16

// ---------------- device scratch (allocation-free) ----------------
__device__ __align__(16) __nv_bfloat16 g_qh[NTOK * DQK];   // Q*0.5 hi
__device__ __align__(16) __nv_bfloat16 g_ql[NTOK * DQK];   // Q*0.5 lo
__device__ __align__(16) __nv_bfloat16 g_kh[NTOK * DQK];
__device__ __align__(16) __nv_bfloat16 g_kl[NTOK * DQK];
__device__ __align__(16) __nv_bfloat16 g_vth[NB * DQK * SEQ];   // [b][feat][tok]
__device__ __align__(16) __nv_bfloat16 g_vtl[NB * DQK * SEQ];
__device__ float2 g_U[48][16][16];

// ---------------- f32x2 packed helpers ----------------
__device__ __forceinline__ unsigned long long pack2(float lo, float hi) {
    unsigned long long r;
    asm("mov.b64 %0, {%1,%2};" : "=l"(r) : "f"(lo), "f"(hi));
    return r;
}
__device__ __forceinline__ void ffma2(unsigned long long& d, unsigned long long a, unsigned long long b) {
    asm("fma.rn.f32x2 %0, %1, %2, %0;" : "+l"(d) : "l"(a), "l"(b));
}
__device__ __forceinline__ float2 unpack2(unsigned long long v) {
    float2 r;
    asm("mov.b64 {%0,%1}, %2;" : "=f"(r.x), "=f"(r.y) : "l"(v));
    return r;
}

// ---------------- complex gate helpers ----------------
__device__ __forceinline__ void gate_rx(float2* v, int w, float ch, float sh) {
    int bit = 8 >> w;
#pragma unroll
    for (int n = 0; n < 16; n++) if (!(n & bit)) {
        float2 a = v[n], b = v[n | bit];
        v[n]       = make_float2(ch * a.x + sh * b.y, ch * a.y - sh * b.x);
        v[n | bit] = make_float2(ch * b.x + sh * a.y, ch * b.y - sh * a.x);
    }
}
__device__ __forceinline__ void gate_ry(float2* v, int w, float ch, float sh) {
    int bit = 8 >> w;
#pragma unroll
    for (int n = 0; n < 16; n++) if (!(n & bit)) {
        float2 a = v[n], b = v[n | bit];
        v[n]       = make_float2(ch * a.x - sh * b.x, ch * a.y - sh * b.y);
        v[n | bit] = make_float2(sh * a.x + ch * b.x, sh * a.y + ch * b.y);
    }
}
__device__ __forceinline__ void gate_rz(float2* v, int w, float ch, float sh) {
    int bit = 8 >> w;
#pragma unroll
    for (int n = 0; n < 16; n++) {
        float2 a = v[n];
        if (n & bit) v[n] = make_float2(ch * a.x - sh * a.y, ch * a.y + sh * a.x);
        else         v[n] = make_float2(ch * a.x + sh * a.y, ch * a.y - sh * a.x);
    }
}
__device__ __forceinline__ void gate_h(float2* v, int w) {
    int bit = 8 >> w;
    const float r = 0.70710678118654752440f;
#pragma unroll
    for (int n = 0; n < 16; n++) if (!(n & bit)) {
        float2 a = v[n], b = v[n | bit];
        v[n]       = make_float2(r * (a.x + b.x), r * (a.y + b.y));
        v[n | bit] = make_float2(r * (a.x - b.x), r * (a.y - b.y));
    }
}
__device__ __forceinline__ void gate_crx(float2* v, int c, int g, float ch, float sh) {
    int bc = 8 >> c, bg = 8 >> g;
#pragma unroll
    for (int n = 0; n < 16; n++) if ((n & bc) && !(n & bg)) {
        float2 a = v[n], b = v[n | bg];
        v[n]      = make_float2(ch * a.x + sh * b.y, ch * a.y - sh * b.x);
        v[n | bg] = make_float2(ch * b.x + sh * a.y, ch * b.y - sh * a.x);
    }
}
__device__ __forceinline__ void gate_cphase_cs(float2* v, int j, int i, float cp, float sp) {
    int bj = 8 >> j, bi = 8 >> i;
#pragma unroll
    for (int n = 0; n < 16; n++) if ((n & bj) && (n & bi)) {
        float2 a = v[n];
        v[n] = make_float2(cp * a.x - sp * a.y, cp * a.y + sp * a.x);
    }
}
__device__ __forceinline__ void gate_iswap(float2* v, int w0, int w1) {
    int b0 = 8 >> w0, b1 = 8 >> w1;
#pragma unroll
    for (int n = 0; n < 16; n++) if (!(n & b0) && (n & b1)) {
        int m = (n | b0) & ~b1;
        float2 a = v[n], b = v[m];
        v[n] = make_float2(-b.y, b.x);
        v[m] = make_float2(-a.y, a.x);
    }
}
__device__ __forceinline__ void gate_swap(float2* v, int w0, int w1) {
    int b0 = 8 >> w0, b1 = 8 >> w1;
#pragma unroll
    for (int n = 0; n < 16; n++) if (!(n & b0) && (n & b1)) {
        int m = (n | b0) & ~b1;
        float2 t = v[n]; v[n] = v[m]; v[m] = t;
    }
}

#define CP1 0.0f
#define SP1 1.0f
#define CP2 0.70710678118654752440f
#define SP2 0.70710678118654752440f
#define CP3 0.92387953251128675613f
#define SP3 0.38268343236508977173f

// ---------------- Kernel A: build 48 fixed 16x16 unitaries ----------------
__global__ void __launch_bounds__(16) build_U_kernel(const float* __restrict__ W,
                                                     const float* __restrict__ EW,
                                                     const float* __restrict__ TW) {
    const int u   = blockIdx.x;
    const int col = threadIdx.x;
    const float* w  = W  + u * 12;
    const float* ew = EW + u * 12;
    const float* tw = TW + u * 12;

    float2 v[16];
#pragma unroll
    for (int n = 0; n < 16; n++) v[n] = make_float2(n == col ? 1.f : 0.f, 0.f);

#pragma unroll
    for (int L = 0; L < 3; L++) {
#pragma unroll
        for (int i = 0; i < 4; i++) {
            float sh, ch;
            __sincosf(0.5f * w[L * 4 + i], &sh, &ch);
            gate_rx(v, i, ch, sh);
            gate_ry(v, i, ch, sh);
            gate_rz(v, i, ch, sh);
        }
#pragma unroll
        for (int i = 0; i < 4; i++) {
            float sh, ch;
            __sincosf(0.5f * ew[L * 4 + i], &sh, &ch);
            gate_crx(v, i, (i + 2) & 3, ch, sh);
            gate_crx(v, i, (i + 3) & 3, ch, sh);
        }
        gate_iswap(v, 0, 1); gate_iswap(v, 1, 2); gate_iswap(v, 2, 3); gate_iswap(v, 3, 0);
        { float2 t = v[12]; v[12] = v[14]; v[14] = t;
          t = v[13]; v[13] = v[15]; v[15] = t; }
#pragma unroll
        for (int i = 0; i < 3; i++) {
            float sh, ch;
            __sincosf(0.5f * tw[L * 4 + i], &sh, &ch);
            gate_crx(v, i, i + 1, ch, sh);
        }
        { float sh, ch; __sincosf(0.5f * tw[L * 4 + 3], &sh, &ch); gate_crx(v, 3, 0, ch, sh); }
#pragma unroll
        for (int i = 0; i < 4; i++) gate_h(v, i);
        gate_cphase_cs(v, 0, 1, CP1, SP1);
        gate_cphase_cs(v, 0, 2, CP2, SP2); gate_cphase_cs(v, 1, 2, CP1, SP1);
        gate_cphase_cs(v, 0, 3, CP3, SP3); gate_cphase_cs(v, 1, 3, CP2, SP2); gate_cphase_cs(v, 2, 3, CP1, SP1);
        gate_swap(v, 0, 3); gate_swap(v, 1, 2);
        gate_h(v, 0);
        gate_h(v, 1); gate_cphase_cs(v, 0, 1, CP1, -SP1);
        gate_h(v, 2); gate_cphase_cs(v, 0, 2, CP2, -SP2); gate_cphase_cs(v, 1, 2, CP1, -SP1);
        gate_h(v, 3); gate_cphase_cs(v, 0, 3, CP3, -SP3); gate_cphase_cs(v, 1, 3, CP2, -SP2); gate_cphase_cs(v, 2, 3, CP1, -SP1);
    }

#pragma unroll
    for (int n = 0; n < 16; n++) g_U[u][n][col] = v[n];
}

// ---------------- Kernel B: per-token QKV, bf16 hi/lo outputs ----------------
__global__ void __launch_bounds__(128) qkv_kernel(const float* __restrict__ x) {
    const int sp  = blockIdx.x;
    const int t0  = blockIdx.y * 128;
    const int tid = threadIdx.x;
    const int t   = t0 + tid;

    __shared__ unsigned long long sUp[3][16][16];
    __shared__ unsigned long long sUm[3][16][16];

    for (int r0 = tid; r0 < 768; r0 += 128) {
        int q = r0 >> 8, rem = r0 & 255;
        float2 Uv = g_U[q * 16 + sp][rem >> 4][rem & 15];
        sUp[q][rem >> 4][rem & 15] = pack2(Uv.x, Uv.x);
        sUm[q][rem >> 4][rem & 15] = pack2(-Uv.y, Uv.y);
    }
    __syncthreads();

    const float4 xv = reinterpret_cast<const float4*>(x)[(size_t)t * 16 + sp];
    float cs[4], sn[4];
    __sincosf(0.5f * xv.x, &sn[0], &cs[0]);
    __sincosf(0.5f * xv.y, &sn[1], &cs[1]);
    __sincosf(0.5f * xv.z, &sn[2], &cs[2]);
    __sincosf(0.5f * xv.w, &sn[3], &cs[3]);

    unsigned long long ep[16], er[16];
#pragma unroll
    for (int n = 0; n < 16; n++) {
        float m = (n & 8 ? sn[0] : cs[0]) * (n & 4 ? sn[1] : cs[1]) *
                  (n & 2 ? sn[2] : cs[2]) * (n & 1 ? sn[3] : cs[3]);
        int pc = __popc(n) & 3;
        float ex = (pc == 0) ? m : (pc == 2) ? -m : 0.f;
        float ey = (pc == 1) ? -m : (pc == 3) ? m : 0.f;
        ep[n] = pack2(ex, ey);
        er[n] = pack2(ey, ex);
    }

#pragma unroll
    for (int q = 0; q < 3; q++) {
        float2 psi[16];
#pragma unroll
        for (int r = 0; r < 16; r++) {
            unsigned long long acc = pack2(0.f, 0.f);
#pragma unroll
            for (int k = 0; k < 16; k++) {
                ffma2(acc, sUp[q][r][k], ep[k]);
                ffma2(acc, sUm[q][r][k], er[k]);
            }
            psi[r] = unpack2(acc);
        }
        float o[12];
#pragma unroll
        for (int w = 0; w < 4; w++) {
            int bit = 8 >> w;
            float z = 0.f, xr = 0.f, yi = 0.f;
#pragma unroll
            for (int n = 0; n < 16; n++) {
                if (n & bit) continue;
                float2 a = psi[n], b = psi[n | bit];
                z  += (a.x * a.x + a.y * a.y) - (b.x * b.x + b.y * b.y);
                xr += a.x * b.x + a.y * b.y;
                yi += a.x * b.y - a.y * b.x;
            }
            o[w] = z; o[4 + w] = 2.f * xr; o[8 + w] = 2.f * yi;
        }
        if (q == 0) {
            // fold scores scale 1/sqrt(NQ)=0.5 into Q
            __nv_bfloat16* bh = g_qh + (size_t)t * DQK + sp * 12;
            __nv_bfloat16* bl = g_ql + (size_t)t * DQK + sp * 12;
#pragma unroll
            for (int m = 0; m < 12; m++) {
                float f = 0.5f * o[m];
                __nv_bfloat16 h = __float2bfloat16(f);
                bh[m] = h;
                bl[m] = __float2bfloat16(f - __bfloat162float(h));
            }
        } else if (q == 1) {
            __nv_bfloat16* bh = g_kh + (size_t)t * DQK + sp * 12;
            __nv_bfloat16* bl = g_kl + (size_t)t * DQK + sp * 12;
#pragma unroll
            for (int m = 0; m < 12; m++) {
                __nv_bfloat16 h = __float2bfloat16(o[m]);
                bh[m] = h;
                bl[m] = __float2bfloat16(o[m] - __bfloat162float(h));
            }
        } else {
            // transposed V: [b][feat][tok], coalesced across tid
            size_t base = ((size_t)(t >> 10) * DQK + sp * 12) * SEQ + (t & 1023);
#pragma unroll
            for (int m = 0; m < 12; m++) {
                __nv_bfloat16 h = __float2bfloat16(o[m]);
                g_vth[base + (size_t)m * SEQ] = h;
                g_vtl[base + (size_t)m * SEQ] = __float2bfloat16(o[m] - __bfloat162float(h));
            }
        }
    }
}

// ---------------- Kernel C1: scores via WMMA bf16-split ----------------
// Tile M=128, N=128, K=192 resident. 256 threads = 8 warps (4m x 2n), warp tile 32x64.
#define SC_LD   200                       // padded row length (bf16 elems)
#define SC_TB   (128 * SC_LD * 2)         // 51200 bytes per tile
#define SC_SMEM (4 * SC_TB)               // 204800

__global__ void __launch_bounds__(256) scores_wmma(float* __restrict__ S) {
    extern __shared__ __align__(16) char dsm[];
    __nv_bfloat16* sQh = (__nv_bfloat16*)(dsm);
    __nv_bfloat16* sQl = (__nv_bfloat16*)(dsm + SC_TB);
    __nv_bfloat16* sKh = (__nv_bfloat16*)(dsm + 2 * SC_TB);
    __nv_bfloat16* sKl = (__nv_bfloat16*)(dsm + 3 * SC_TB);

    const int tid = threadIdx.x, wid = tid >> 5;
    const int b = blockIdx.z, m0 = blockIdx.y * 128, n0 = blockIdx.x * 128;

    const uint4* gQh = (const uint4*)(g_qh + (size_t)(b * SEQ + m0) * DQK);
    const uint4* gQl = (const uint4*)(g_ql + (size_t)(b * SEQ + m0) * DQK);
    const uint4* gKh = (const uint4*)(g_kh + (size_t)(b * SEQ + n0) * DQK);
    const uint4* gKl = (const uint4*)(g_kl + (size_t)(b * SEQ + n0) * DQK);

#pragma unroll
    for (int i = 0; i < 12; i++) {
        int idx = i * 256 + tid;                 // 3072 = 128 rows * 24 c16
        int r = idx / 24, c16 = idx % 24;
        int g = r * 24 + c16;
        int so = r * SC_LD + c16 * 8;            // bf16 elem offset, 16B aligned
        *(uint4*)(sQh + so) = gQh[g];
        *(uint4*)(sQl + so) = gQl[g];
        *(uint4*)(sKh + so) = gKh[g];
        *(uint4*)(sKl + so) = gKl[g];
    }
    __syncthreads();

    const int wm = wid >> 1, wn = wid & 1;       // 4 x 2
    const int mb = wm * 32, nb = wn * 64;

    wmma::fragment<wmma::accumulator, 16, 16, 16, float> acc[2][4];
#pragma unroll
    for (int i = 0; i < 2; i++)
#pragma unroll
        for (int j = 0; j < 4; j++) wmma::fill_fragment(acc[i][j], 0.f);

    wmma::fragment<wmma::matrix_a, 16, 16, 16, __nv_bfloat16, wmma::row_major> ah[2], al[2];
    wmma::fragment<wmma::matrix_b, 16, 16, 16, __nv_bfloat16, wmma::col_major> bh[4], bl[4];

#pragma unroll
    for (int ks = 0; ks < 12; ks++) {
        const int k0 = ks * 16;
#pragma unroll
        for (int i = 0; i < 2; i++) {
            wmma::load_matrix_sync(ah[i], sQh + (mb + i * 16) * SC_LD + k0, SC_LD);
            wmma::load_matrix_sync(al[i], sQl + (mb + i * 16) * SC_LD + k0, SC_LD);
        }
#pragma unroll
        for (int j = 0; j < 4; j++) {
            wmma::load_matrix_sync(bh[j], sKh + (nb + j * 16) * SC_LD + k0, SC_LD);
            wmma::load_matrix_sync(bl[j], sKl + (nb + j * 16) * SC_LD + k0, SC_LD);
        }
#pragma unroll
        for (int i = 0; i < 2; i++)
#pragma unroll
            for (int j = 0; j < 4; j++) {
                wmma::mma_sync(acc[i][j], ah[i], bh[j], acc[i][j]);
                wmma::mma_sync(acc[i][j], ah[i], bl[j], acc[i][j]);
                wmma::mma_sync(acc[i][j], al[i], bh[j], acc[i][j]);
            }
    }

    float* Sp = S + ((size_t)b << 20);
#pragma unroll
    for (int i = 0; i < 2; i++)
#pragma unroll
        for (int j = 0; j < 4; j++)
            wmma::store_matrix_sync(Sp + (size_t)(m0 + mb + i * 16) * SEQ + n0 + nb + j * 16,
                                    acc[i][j], SEQ, wmma::mem_row_major);
}

// ---------------- Kernel C2: in-place row softmax over 1024 ----------------
__global__ void __launch_bounds__(256) softmax_kernel(float* __restrict__ A) {
    const int row = blockIdx.x;
    float* p = A + (size_t)row * SEQ;
    const int t = threadIdx.x;

    float4 v = *reinterpret_cast<float4*>(p + t * 4);
    float mx = fmaxf(fmaxf(v.x, v.y), fmaxf(v.z, v.w));
#pragma unroll
    for (int o = 16; o; o >>= 1) mx = fmaxf(mx, __shfl_xor_sync(0xffffffffu, mx, o));

    __shared__ float red[8];
    __shared__ float bmax, bsum;
    if ((t & 31) == 0) red[t >> 5] = mx;
    __syncthreads();
    if (t < 8) {
        float m = red[t];
#pragma unroll
        for (int o = 4; o; o >>= 1) m = fmaxf(m, __shfl_xor_sync(0xffu, m, o));
        if (t == 0) bmax = m;
    }
    __syncthreads();
    const float M = bmax;

    float e0 = expf(v.x - M), e1 = expf(v.y - M), e2 = expf(v.z - M), e3 = expf(v.w - M);
    float s = e0 + e1 + e2 + e3;
#pragma unroll
    for (int o = 16; o; o >>= 1) s += __shfl_xor_sync(0xffffffffu, s, o);
    if ((t & 31) == 0) red[t >> 5] = s;
    __syncthreads();
    if (t < 8) {
        float m = red[t];
#pragma unroll
        for (int o = 4; o; o >>= 1) m += __shfl_xor_sync(0xffu, m, o);
        if (t == 0) bsum = m;
    }
    __syncthreads();
    const float inv = 1.f / bsum;
    *reinterpret_cast<float4*>(p + t * 4) = make_float4(e0 * inv, e1 * inv, e2 * inv, e3 * inv);
}

// ---------------- Kernel C3: O = P @ V via WMMA bf16-split + fused LN ----------------
// Tile M=128, N=192, K=1024 in 8 chunks of 128. 256 threads = 8 warps (4m x 2n),
// warp tile 32x96.
#define O_LD    136                           // padded k-chunk row (bf16 elems)
#define O_PB    (128 * O_LD * 2)              // 34816
#define O_VB    (192 * O_LD * 2)              // 52224
#define O_SPH   0
#define O_SPL   (O_SPH + O_PB)
#define O_SVH   (O_SPL + O_PB)
#define O_SVL   (O_SVH + O_VB)
#define O_GAM   (O_SVL + O_VB)                // 174080
#define O_BET   (O_GAM + 768)
#define O_SMEM  (O_BET + 768)                 // 175616
#define O_OLD   200                           // f32 staging row

__global__ void __launch_bounds__(256) o_wmma(const float* __restrict__ A, float* __restrict__ O,
                                              const float* __restrict__ gamma,
                                              const float* __restrict__ beta) {
    extern __shared__ __align__(16) char dsm[];
    __nv_bfloat16* sPh = (__nv_bfloat16*)(dsm + O_SPH);
    __nv_bfloat16* sPl = (__nv_bfloat16*)(dsm + O_SPL);
    __nv_bfloat16* sVh = (__nv_bfloat16*)(dsm + O_SVH);
    __nv_bfloat16* sVl = (__nv_bfloat16*)(dsm + O_SVL);
    float* sg  = (float*)(dsm + O_GAM);
    float* sbt = (float*)(dsm + O_BET);
    float* sOut = (float*)(dsm);               // reused after mainloop

    const int tid = threadIdx.x, wid = tid >> 5, lane = tid & 31;
    const int b = blockIdx.y, m0 = blockIdx.x * 128;

    if (tid < 192) { sg[tid] = gamma[tid]; sbt[tid] = beta[tid]; }

    const float4* Ab4 = (const float4*)(A + ((size_t)b << 20) + (size_t)m0 * SEQ);
    const uint4*  Vh4 = (const uint4*)(g_vth + (size_t)b * DQK * SEQ);
    const uint4*  Vl4 = (const uint4*)(g_vtl + (size_t)b * DQK * SEQ);

    const int wm = wid >> 1, wn = wid & 1;     // 4 x 2
    const int mb = wm * 32, nb = wn * 96;

    wmma::fragment<wmma::accumulator, 16, 16, 16, float> acc[2][6];
#pragma unroll
    for (int i = 0; i < 2; i++)
#pragma unroll
        for (int j = 0; j < 6; j++) wmma::fill_fragment(acc[i][j], 0.f);

    for (int chunk = 0; chunk < 8; chunk++) {
        const int k0 = chunk * 128;
        __syncthreads();
        // P: 128 rows x 128 fp32 -> bf16 hi/lo
#pragma unroll
        for (int i = 0; i < 8; i++) {
            int idx = i * 256 + tid;             // 2048 = 128 rows * 16 float4-pairs
            int r = idx >> 4, c8 = idx & 15;     // c8: 8 floats each
            float4 u = Ab4[r * 256 + (k0 >> 2) + c8 * 2];
            float4 w = Ab4[r * 256 + (k0 >> 2) + c8 * 2 + 1];
            __nv_bfloat162 h0 = __float22bfloat162_rn(make_float2(u.x, u.y));
            __nv_bfloat162 h1 = __float22bfloat162_rn(make_float2(u.z, u.w));
            __nv_bfloat162 h2 = __float22bfloat162_rn(make_float2(w.x, w.y));
            __nv_bfloat162 h3 = __float22bfloat162_rn(make_float2(w.z, w.w));
            float2 f0 = __bfloat1622float2(h0), f1 = __bfloat1622float2(h1);
            float2 f2 = __bfloat1622float2(h2), f3 = __bfloat1622float2(h3);
            __nv_bfloat162 l0 = __float22bfloat162_rn(make_float2(u.x - f0.x, u.y - f0.y));
            __nv_bfloat162 l1 = __float22bfloat162_rn(make_float2(u.z - f1.x, u.w - f1.y));
            __nv_bfloat162 l2 = __float22bfloat162_rn(make_float2(w.x - f2.x, w.y - f2.y));
            __nv_bfloat162 l3 = __float22bfloat162_rn(make_float2(w.z - f3.x, w.w - f3.y));
            int so = r * O_LD + c8 * 8;          // 16B aligned
            *(uint4*)(sPh + so) = make_uint4(*(uint32_t*)&h0, *(uint32_t*)&h1, *(uint32_t*)&h2, *(uint32_t*)&h3);
            *(uint4*)(sPl + so) = make_uint4(*(uint32_t*)&l0, *(uint32_t*)&l1, *(uint32_t*)&l2, *(uint32_t*)&l3);
        }
        // V: 192 feat rows x 128 toks (K-major)
#pragma unroll
        for (int i = 0; i < 12; i++) {
            int idx = i * 256 + tid;             // 3072 = 192 rows * 16 c16
            int n = idx >> 4, c16 = idx & 15;
            int g = n * 128 + (k0 >> 3) + c16;
            int so = n * O_LD + c16 * 8;
            *(uint4*)(sVh + so) = Vh4[g];
            *(uint4*)(sVl + so) = Vl4[g];
        }
        __syncthreads();

        wmma::fragment<wmma::matrix_a, 16, 16, 16, __nv_bfloat16, wmma::row_major> ah[2], al[2];
        wmma::fragment<wmma::matrix_b, 16, 16, 16, __nv_bfloat16, wmma::col_major> bh, bl;
#pragma unroll
        for (int ks = 0; ks < 8; ks++) {
            const int kk = ks * 16;
#pragma unroll
            for (int i = 0; i < 2; i++) {
                wmma::load_matrix_sync(ah[i], sPh + (mb + i * 16) * O_LD + kk, O_LD);
                wmma::load_matrix_sync(al[i], sPl + (mb + i * 16) * O_LD + kk, O_LD);
            }
#pragma unroll
            for (int j = 0; j < 6; j++) {
                wmma::load_matrix_sync(bh, sVh + (nb + j * 16) * O_LD + kk, O_LD);
                wmma::load_matrix_sync(bl, sVl + (nb + j * 16) * O_LD + kk, O_LD);
#pragma unroll
                for (int i = 0; i < 2; i++) {
                    wmma::mma_sync(acc[i][j], ah[i], bh, acc[i][j]);
                    wmma::mma_sync(acc[i][j], ah[i], bl, acc[i][j]);
                    wmma::mma_sync(acc[i][j], al[i], bh, acc[i][j]);
                }
            }
        }
    }
    __syncthreads();

    // stage to smem f32 [128][200]
#pragma unroll
    for (int i = 0; i < 2; i++)
#pragma unroll
        for (int j = 0; j < 6; j++)
            wmma::store_matrix_sync(sOut + (mb + i * 16) * O_OLD + nb + j * 16,
                                    acc[i][j], O_OLD, wmma::mem_row_major);
    __syncthreads();

    // fused LayerNorm: warp per row, 16 rows per warp
    for (int it = 0; it < 16; it++) {
        const int r = wid + it * 8;
        const float* rowp = sOut + r * O_OLD + lane * 6;
        float f[6];
#pragma unroll
        for (int e = 0; e < 6; e++) f[e] = rowp[e];
        float s = 0.f, s2 = 0.f;
#pragma unroll
        for (int e = 0; e < 6; e++) { s += f[e]; s2 += f[e] * f[e]; }
#pragma unroll
        for (int o = 16; o; o >>= 1) {
            s  += __shfl_xor_sync(0xffffffffu, s, o);
            s2 += __shfl_xor_sync(0xffffffffu, s2, o);
        }
        float mean = s * (1.f / 192.f);
        float var  = s2 * (1.f / 192.f) - mean * mean;
        float rstd = rsqrtf(var + 1e-5f);
        float* orow = O + (size_t)(b * SEQ + m0 + r) * DQK + lane * 6;
#pragma unroll
        for (int e = 0; e < 6; e += 2) {
            float2 w;
            w.x = (f[e]     - mean) * rstd * sg[lane * 6 + e]     + sbt[lane * 6 + e];
            w.y = (f[e + 1] - mean) * rstd * sg[lane * 6 + e + 1] + sbt[lane * 6 + e + 1];
            *(float2*)(orow + e) = w;
        }
    }
}

// ---------------- launch ----------------
extern "C" void kernel_launch(void* const* d_in, const int* in_sizes, int n_in,
                              void* d_out, int out_size) {
    const float* x     = (const float*)d_in[0];
    const float* w     = (const float*)d_in[1];
    const float* ew    = (const float*)d_in[2];
    const float* tw    = (const float*)d_in[3];
    const float* gamma = (const float*)d_in[4];
    const float* beta  = (const float*)d_in[5];
    (void)in_sizes; (void)n_in; (void)out_size;

    float* out      = (float*)d_out;
    float* out_o    = out;                                  // [16,1024,192]
    float* out_attn = out + (size_t)NTOK * DQK;             // [16,1024,1024]

    cudaFuncSetAttribute(scores_wmma, cudaFuncAttributeMaxDynamicSharedMemorySize, SC_SMEM);
    cudaFuncSetAttribute(o_wmma,      cudaFuncAttributeMaxDynamicSharedMemorySize, O_SMEM);

    build_U_kernel<<<48, 16>>>(w, ew, tw);
    qkv_kernel<<<dim3(16, NTOK / 128), 128>>>(x);
    scores_wmma<<<dim3(8, 8, 16), 256, SC_SMEM>>>(out_attn);
    softmax_kernel<<<NTOK, 256>>>(out_attn);
    o_wmma<<<dim3(8, 16), 256, O_SMEM>>>(out_attn, out_o, gamma, beta);
}

// round 8
// speedup vs baseline: 2.6522x; 1.1030x over previous
#include <cuda_runtime.h>
#include <cuda_bf16.h>
#include <mma.h>
#include <math.h>
#include <stdint.h>

using namespace nvcuda;

// Problem dims
#define NTOK 16384          // B*S
#define DQK  192
#define SEQ  1024
#define NB   16

// ---------------- device scratch (allocation-free) ----------------
__device__ __align__(16) __nv_bfloat16 g_qh[NTOK * DQK];   // Q*0.5 hi
__device__ __align__(16) __nv_bfloat16 g_ql[NTOK * DQK];   // Q*0.5 lo
__device__ __align__(16) __nv_bfloat16 g_kh[NTOK * DQK];
__device__ __align__(16) __nv_bfloat16 g_kl[NTOK * DQK];
__device__ __align__(16) __nv_bfloat16 g_vth[NB * DQK * SEQ];   // [b][feat][tok]
__device__ __align__(16) __nv_bfloat16 g_vtl[NB * DQK * SEQ];
__device__ float2 g_U[48][16][16];   // PHASE-ABSORBED: U'[r][k] = U[r][k]*(-i)^popc(k)

// ---------------- packed helpers ----------------
__device__ __forceinline__ unsigned long long pack2(float lo, float hi) {
    unsigned long long r;
    asm("mov.b64 %0, {%1,%2};" : "=l"(r) : "f"(lo), "f"(hi));
    return r;
}
__device__ __forceinline__ void ffma2(unsigned long long& d, unsigned long long a, unsigned long long b) {
    asm("fma.rn.f32x2 %0, %1, %2, %0;" : "+l"(d) : "l"(a), "l"(b));
}
__device__ __forceinline__ float2 unpack2(unsigned long long v) {
    float2 r;
    asm("mov.b64 {%0,%1}, %2;" : "=f"(r.x), "=f"(r.y) : "l"(v));
    return r;
}
__device__ __forceinline__ uint32_t smem_u32(const void* p) {
    uint32_t a;
    asm("{ .reg .u64 t; cvta.to.shared.u64 t, %1; cvt.u32.u64 %0, t; }" : "=r"(a) : "l"(p));
    return a;
}
__device__ __forceinline__ void cp_async16(uint32_t sm, const void* g) {
    asm volatile("cp.async.cg.shared.global [%0], [%1], 16;" :: "r"(sm), "l"(g) : "memory");
}
#define CP_COMMIT() asm volatile("cp.async.commit_group;" ::: "memory")
#define CP_WAIT0()  asm volatile("cp.async.wait_group 0;" ::: "memory")

// ---------------- complex gate helpers ----------------
__device__ __forceinline__ void gate_rx(float2* v, int w, float ch, float sh) {
    int bit = 8 >> w;
#pragma unroll
    for (int n = 0; n < 16; n++) if (!(n & bit)) {
        float2 a = v[n], b = v[n | bit];
        v[n]       = make_float2(ch * a.x + sh * b.y, ch * a.y - sh * b.x);
        v[n | bit] = make_float2(ch * b.x + sh * a.y, ch * b.y - sh * a.x);
    }
}
__device__ __forceinline__ void gate_ry(float2* v, int w, float ch, float sh) {
    int bit = 8 >> w;
#pragma unroll
    for (int n = 0; n < 16; n++) if (!(n & bit)) {
        float2 a = v[n], b = v[n | bit];
        v[n]       = make_float2(ch * a.x - sh * b.x, ch * a.y - sh * b.y);
        v[n | bit] = make_float2(sh * a.x + ch * b.x, sh * a.y + ch * b.y);
    }
}
__device__ __forceinline__ void gate_rz(float2* v, int w, float ch, float sh) {
    int bit = 8 >> w;
#pragma unroll
    for (int n = 0; n < 16; n++) {
        float2 a = v[n];
        if (n & bit) v[n] = make_float2(ch * a.x - sh * a.y, ch * a.y + sh * a.x);
        else         v[n] = make_float2(ch * a.x + sh * a.y, ch * a.y - sh * a.x);
    }
}
__device__ __forceinline__ void gate_h(float2* v, int w) {
    int bit = 8 >> w;
    const float r = 0.70710678118654752440f;
#pragma unroll
    for (int n = 0; n < 16; n++) if (!(n & bit)) {
        float2 a = v[n], b = v[n | bit];
        v[n]       = make_float2(r * (a.x + b.x), r * (a.y + b.y));
        v[n | bit] = make_float2(r * (a.x - b.x), r * (a.y - b.y));
    }
}
__device__ __forceinline__ void gate_crx(float2* v, int c, int g, float ch, float sh) {
    int bc = 8 >> c, bg = 8 >> g;
#pragma unroll
    for (int n = 0; n < 16; n++) if ((n & bc) && !(n & bg)) {
        float2 a = v[n], b = v[n | bg];
        v[n]      = make_float2(ch * a.x + sh * b.y, ch * a.y - sh * b.x);
        v[n | bg] = make_float2(ch * b.x + sh * a.y, ch * b.y - sh * a.x);
    }
}
__device__ __forceinline__ void gate_cphase_cs(float2* v, int j, int i, float cp, float sp) {
    int bj = 8 >> j, bi = 8 >> i;
#pragma unroll
    for (int n = 0; n < 16; n++) if ((n & bj) && (n & bi)) {
        float2 a = v[n];
        v[n] = make_float2(cp * a.x - sp * a.y, cp * a.y + sp * a.x);
    }
}
__device__ __forceinline__ void gate_iswap(float2* v, int w0, int w1) {
    int b0 = 8 >> w0, b1 = 8 >> w1;
#pragma unroll
    for (int n = 0; n < 16; n++) if (!(n & b0) && (n & b1)) {
        int m = (n | b0) & ~b1;
        float2 a = v[n], b = v[m];
        v[n] = make_float2(-b.y, b.x);
        v[m] = make_float2(-a.y, a.x);
    }
}
__device__ __forceinline__ void gate_swap(float2* v, int w0, int w1) {
    int b0 = 8 >> w0, b1 = 8 >> w1;
#pragma unroll
    for (int n = 0; n < 16; n++) if (!(n & b0) && (n & b1)) {
        int m = (n | b0) & ~b1;
        float2 t = v[n]; v[n] = v[m]; v[m] = t;
    }
}

#define CP1 0.0f
#define SP1 1.0f
#define CP2 0.70710678118654752440f
#define SP2 0.70710678118654752440f
#define CP3 0.92387953251128675613f
#define SP3 0.38268343236508977173f

// ---------------- Kernel A: build 48 phase-absorbed 16x16 unitaries ----------------
__global__ void __launch_bounds__(16) build_U_kernel(const float* __restrict__ W,
                                                     const float* __restrict__ EW,
                                                     const float* __restrict__ TW) {
    const int u   = blockIdx.x;
    const int col = threadIdx.x;
    const float* w  = W  + u * 12;
    const float* ew = EW + u * 12;
    const float* tw = TW + u * 12;

    float2 v[16];
#pragma unroll
    for (int n = 0; n < 16; n++) v[n] = make_float2(n == col ? 1.f : 0.f, 0.f);

#pragma unroll
    for (int L = 0; L < 3; L++) {
#pragma unroll
        for (int i = 0; i < 4; i++) {
            float sh, ch;
            __sincosf(0.5f * w[L * 4 + i], &sh, &ch);
            gate_rx(v, i, ch, sh);
            gate_ry(v, i, ch, sh);
            gate_rz(v, i, ch, sh);
        }
#pragma unroll
        for (int i = 0; i < 4; i++) {
            float sh, ch;
            __sincosf(0.5f * ew[L * 4 + i], &sh, &ch);
            gate_crx(v, i, (i + 2) & 3, ch, sh);
            gate_crx(v, i, (i + 3) & 3, ch, sh);
        }
        gate_iswap(v, 0, 1); gate_iswap(v, 1, 2); gate_iswap(v, 2, 3); gate_iswap(v, 3, 0);
        { float2 t = v[12]; v[12] = v[14]; v[14] = t;
          t = v[13]; v[13] = v[15]; v[15] = t; }
#pragma unroll
        for (int i = 0; i < 3; i++) {
            float sh, ch;
            __sincosf(0.5f * tw[L * 4 + i], &sh, &ch);
            gate_crx(v, i, i + 1, ch, sh);
        }
        { float sh, ch; __sincosf(0.5f * tw[L * 4 + 3], &sh, &ch); gate_crx(v, 3, 0, ch, sh); }
#pragma unroll
        for (int i = 0; i < 4; i++) gate_h(v, i);
        gate_cphase_cs(v, 0, 1, CP1, SP1);
        gate_cphase_cs(v, 0, 2, CP2, SP2); gate_cphase_cs(v, 1, 2, CP1, SP1);
        gate_cphase_cs(v, 0, 3, CP3, SP3); gate_cphase_cs(v, 1, 3, CP2, SP2); gate_cphase_cs(v, 2, 3, CP1, SP1);
        gate_swap(v, 0, 3); gate_swap(v, 1, 2);
        gate_h(v, 0);
        gate_h(v, 1); gate_cphase_cs(v, 0, 1, CP1, -SP1);
        gate_h(v, 2); gate_cphase_cs(v, 0, 2, CP2, -SP2); gate_cphase_cs(v, 1, 2, CP1, -SP1);
        gate_h(v, 3); gate_cphase_cs(v, 0, 3, CP3, -SP3); gate_cphase_cs(v, 1, 3, CP2, -SP2); gate_cphase_cs(v, 2, 3, CP1, -SP1);
    }

    // absorb e-phase (-i)^popc(col) into column col
    const int pc = __popc(col) & 3;
#pragma unroll
    for (int n = 0; n < 16; n++) {
        float2 a = v[n], r;
        if      (pc == 0) r = a;
        else if (pc == 1) r = make_float2(a.y, -a.x);    // (-i)*a
        else if (pc == 2) r = make_float2(-a.x, -a.y);   // (-1)*a
        else              r = make_float2(-a.y, a.x);    // (+i)*a
        g_U[u][n][col] = r;
    }
}

// ---------------- Kernel B: per-token QKV via real-vector complex matvec ----------------
__global__ void __launch_bounds__(128) qkv_kernel(const float* __restrict__ x) {
    const int sp  = blockIdx.x;
    const int t0  = blockIdx.y * 128;
    const int tid = threadIdx.x;
    const int t   = t0 + tid;

    __shared__ unsigned long long sU2[3][16][16];   // (Ure, Uim) phase-absorbed

    for (int r0 = tid; r0 < 768; r0 += 128) {
        int q = r0 >> 8, rem = r0 & 255;
        float2 Uv = g_U[q * 16 + sp][rem >> 4][rem & 15];
        sU2[q][rem >> 4][rem & 15] = pack2(Uv.x, Uv.y);
    }
    __syncthreads();

    const float4 xv = reinterpret_cast<const float4*>(x)[(size_t)t * 16 + sp];
    float cs[4], sn[4];
    __sincosf(0.5f * xv.x, &sn[0], &cs[0]);
    __sincosf(0.5f * xv.y, &sn[1], &cs[1]);
    __sincosf(0.5f * xv.z, &sn[2], &cs[2]);
    __sincosf(0.5f * xv.w, &sn[3], &cs[3]);

    unsigned long long mm[16];
#pragma unroll
    for (int n = 0; n < 16; n++) {
        float m = (n & 8 ? sn[0] : cs[0]) * (n & 4 ? sn[1] : cs[1]) *
                  (n & 2 ? sn[2] : cs[2]) * (n & 1 ? sn[3] : cs[3]);
        mm[n] = pack2(m, m);
    }

#pragma unroll
    for (int q = 0; q < 3; q++) {
        float2 psi[16];
#pragma unroll
        for (int r = 0; r < 16; r++) {
            unsigned long long acc = 0ull;
#pragma unroll
            for (int k = 0; k < 16; k++) ffma2(acc, sU2[q][r][k], mm[k]);
            psi[r] = unpack2(acc);
        }
        float o[12];
#pragma unroll
        for (int w = 0; w < 4; w++) {
            int bit = 8 >> w;
            float z = 0.f, xr = 0.f, yi = 0.f;
#pragma unroll
            for (int n = 0; n < 16; n++) {
                if (n & bit) continue;
                float2 a = psi[n], b = psi[n | bit];
                z  += (a.x * a.x + a.y * a.y) - (b.x * b.x + b.y * b.y);
                xr += a.x * b.x + a.y * b.y;
                yi += a.x * b.y - a.y * b.x;
            }
            o[w] = z; o[4 + w] = 2.f * xr; o[8 + w] = 2.f * yi;
        }
        if (q == 0) {
            __nv_bfloat16* bh = g_qh + (size_t)t * DQK + sp * 12;
            __nv_bfloat16* bl = g_ql + (size_t)t * DQK + sp * 12;
#pragma unroll
            for (int m = 0; m < 12; m++) {
                float f = 0.5f * o[m];
                __nv_bfloat16 h = __float2bfloat16(f);
                bh[m] = h;
                bl[m] = __float2bfloat16(f - __bfloat162float(h));
            }
        } else if (q == 1) {
            __nv_bfloat16* bh = g_kh + (size_t)t * DQK + sp * 12;
            __nv_bfloat16* bl = g_kl + (size_t)t * DQK + sp * 12;
#pragma unroll
            for (int m = 0; m < 12; m++) {
                __nv_bfloat16 h = __float2bfloat16(o[m]);
                bh[m] = h;
                bl[m] = __float2bfloat16(o[m] - __bfloat162float(h));
            }
        } else {
            size_t base = ((size_t)(t >> 10) * DQK + sp * 12) * SEQ + (t & 1023);
#pragma unroll
            for (int m = 0; m < 12; m++) {
                __nv_bfloat16 h = __float2bfloat16(o[m]);
                g_vth[base + (size_t)m * SEQ] = h;
                g_vtl[base + (size_t)m * SEQ] = __float2bfloat16(o[m] - __bfloat162float(h));
            }
        }
    }
}

// ---------------- Kernel C1: scores via WMMA bf16-split (2-stage K) ----------------
// Tile M=128, N=128; K=192 in 2 stages of 96. 104KB smem -> 2 blocks/SM.
#define SC_LD   104
#define SC_TB   (128 * SC_LD * 2)         // 26624 bytes per tile
#define SC_SMEM (4 * SC_TB)               // 106496

__global__ void __launch_bounds__(256) scores_wmma(float* __restrict__ S) {
    extern __shared__ __align__(16) char dsm[];
    __nv_bfloat16* sQh = (__nv_bfloat16*)(dsm);
    __nv_bfloat16* sQl = (__nv_bfloat16*)(dsm + SC_TB);
    __nv_bfloat16* sKh = (__nv_bfloat16*)(dsm + 2 * SC_TB);
    __nv_bfloat16* sKl = (__nv_bfloat16*)(dsm + 3 * SC_TB);

    const int tid = threadIdx.x, wid = tid >> 5;
    const int b = blockIdx.z, m0 = blockIdx.y * 128, n0 = blockIdx.x * 128;

    const uint4* gQh = (const uint4*)(g_qh + (size_t)(b * SEQ + m0) * DQK);
    const uint4* gQl = (const uint4*)(g_ql + (size_t)(b * SEQ + m0) * DQK);
    const uint4* gKh = (const uint4*)(g_kh + (size_t)(b * SEQ + n0) * DQK);
    const uint4* gKl = (const uint4*)(g_kl + (size_t)(b * SEQ + n0) * DQK);

    const int wm = wid >> 1, wn = wid & 1;       // 4 x 2
    const int mb = wm * 32, nb = wn * 64;

    wmma::fragment<wmma::accumulator, 16, 16, 16, float> acc[2][4];
#pragma unroll
    for (int i = 0; i < 2; i++)
#pragma unroll
        for (int j = 0; j < 4; j++) wmma::fill_fragment(acc[i][j], 0.f);

#pragma unroll
    for (int half = 0; half < 2; half++) {
        if (half) __syncthreads();
#pragma unroll
        for (int i = 0; i < 6; i++) {
            int idx = i * 256 + tid;                 // 1536 = 128 rows * 12 c8
            int r = idx / 12, c8 = idx % 12;
            int g = r * 24 + half * 12 + c8;
            int so = r * SC_LD + c8 * 8;
            *(uint4*)(sQh + so) = gQh[g];
            *(uint4*)(sQl + so) = gQl[g];
            *(uint4*)(sKh + so) = gKh[g];
            *(uint4*)(sKl + so) = gKl[g];
        }
        __syncthreads();

        wmma::fragment<wmma::matrix_a, 16, 16, 16, __nv_bfloat16, wmma::row_major> ah[2], al[2];
        wmma::fragment<wmma::matrix_b, 16, 16, 16, __nv_bfloat16, wmma::col_major> bh[4], bl[4];
#pragma unroll
        for (int ks = 0; ks < 6; ks++) {
            const int k0 = ks * 16;
#pragma unroll
            for (int i = 0; i < 2; i++) {
                wmma::load_matrix_sync(ah[i], sQh + (mb + i * 16) * SC_LD + k0, SC_LD);
                wmma::load_matrix_sync(al[i], sQl + (mb + i * 16) * SC_LD + k0, SC_LD);
            }
#pragma unroll
            for (int j = 0; j < 4; j++) {
                wmma::load_matrix_sync(bh[j], sKh + (nb + j * 16) * SC_LD + k0, SC_LD);
                wmma::load_matrix_sync(bl[j], sKl + (nb + j * 16) * SC_LD + k0, SC_LD);
            }
#pragma unroll
            for (int i = 0; i < 2; i++)
#pragma unroll
                for (int j = 0; j < 4; j++) {
                    wmma::mma_sync(acc[i][j], ah[i], bh[j], acc[i][j]);
                    wmma::mma_sync(acc[i][j], ah[i], bl[j], acc[i][j]);
                    wmma::mma_sync(acc[i][j], al[i], bh[j], acc[i][j]);
                }
        }
    }

    float* Sp = S + ((size_t)b << 20);
#pragma unroll
    for (int i = 0; i < 2; i++)
#pragma unroll
        for (int j = 0; j < 4; j++)
            wmma::store_matrix_sync(Sp + (size_t)(m0 + mb + i * 16) * SEQ + n0 + nb + j * 16,
                                    acc[i][j], SEQ, wmma::mem_row_major);
}

// ---------------- Kernel C2: in-place row softmax over 1024 ----------------
__global__ void __launch_bounds__(256) softmax_kernel(float* __restrict__ A) {
    const int row = blockIdx.x;
    float* p = A + (size_t)row * SEQ;
    const int t = threadIdx.x;

    float4 v = *reinterpret_cast<float4*>(p + t * 4);
    float mx = fmaxf(fmaxf(v.x, v.y), fmaxf(v.z, v.w));
#pragma unroll
    for (int o = 16; o; o >>= 1) mx = fmaxf(mx, __shfl_xor_sync(0xffffffffu, mx, o));

    __shared__ float red[8];
    __shared__ float bmax, bsum;
    if ((t & 31) == 0) red[t >> 5] = mx;
    __syncthreads();
    if (t < 8) {
        float m = red[t];
#pragma unroll
        for (int o = 4; o; o >>= 1) m = fmaxf(m, __shfl_xor_sync(0xffu, m, o));
        if (t == 0) bmax = m;
    }
    __syncthreads();
    const float M = bmax;

    float e0 = expf(v.x - M), e1 = expf(v.y - M), e2 = expf(v.z - M), e3 = expf(v.w - M);
    float s = e0 + e1 + e2 + e3;
#pragma unroll
    for (int o = 16; o; o >>= 1) s += __shfl_xor_sync(0xffffffffu, s, o);
    if ((t & 31) == 0) red[t >> 5] = s;
    __syncthreads();
    if (t < 8) {
        float m = red[t];
#pragma unroll
        for (int o = 4; o; o >>= 1) m += __shfl_xor_sync(0xffu, m, o);
        if (t == 0) bsum = m;
    }
    __syncthreads();
    const float inv = 1.f / bsum;
    *reinterpret_cast<float4*>(p + t * 4) = make_float4(e0 * inv, e1 * inv, e2 * inv, e3 * inv);
}

// ---------------- Kernel C3: O = P @ V via WMMA bf16-split + cp.async + fused LN ----------------
#define O_LD    136
#define O_PB    (128 * O_LD * 2)              // 34816
#define O_VB    (192 * O_LD * 2)              // 52224
#define O_SPH   0
#define O_SPL   (O_SPH + O_PB)
#define O_SVH   (O_SPL + O_PB)
#define O_SVL   (O_SVH + O_VB)
#define O_GAM   (O_SVL + O_VB)                // 174080
#define O_BET   (O_GAM + 768)
#define O_SMEM  (O_BET + 768)                 // 175616
#define O_OLD   200

__global__ void __launch_bounds__(256) o_wmma(const float* __restrict__ A, float* __restrict__ O,
                                              const float* __restrict__ gamma,
                                              const float* __restrict__ beta) {
    extern __shared__ __align__(16) char dsm[];
    __nv_bfloat16* sPh = (__nv_bfloat16*)(dsm + O_SPH);
    __nv_bfloat16* sPl = (__nv_bfloat16*)(dsm + O_SPL);
    __nv_bfloat16* sVh = (__nv_bfloat16*)(dsm + O_SVH);
    __nv_bfloat16* sVl = (__nv_bfloat16*)(dsm + O_SVL);
    float* sg  = (float*)(dsm + O_GAM);
    float* sbt = (float*)(dsm + O_BET);
    float* sOut = (float*)(dsm);

    const int tid = threadIdx.x, wid = tid >> 5, lane = tid & 31;
    const int b = blockIdx.y, m0 = blockIdx.x * 128;

    if (tid < 192) { sg[tid] = gamma[tid]; sbt[tid] = beta[tid]; }

    const float4* Ab4 = (const float4*)(A + ((size_t)b << 20) + (size_t)m0 * SEQ);
    const uint4*  Vh4 = (const uint4*)(g_vth + (size_t)b * DQK * SEQ);
    const uint4*  Vl4 = (const uint4*)(g_vtl + (size_t)b * DQK * SEQ);
    const uint32_t svh_u = smem_u32(sVh), svl_u = smem_u32(sVl);

    const int wm = wid >> 1, wn = wid & 1;
    const int mb = wm * 32, nb = wn * 96;

    wmma::fragment<wmma::accumulator, 16, 16, 16, float> acc[2][6];
#pragma unroll
    for (int i = 0; i < 2; i++)
#pragma unroll
        for (int j = 0; j < 6; j++) wmma::fill_fragment(acc[i][j], 0.f);

    for (int chunk = 0; chunk < 8; chunk++) {
        const int k0 = chunk * 128;
        __syncthreads();
        // V via cp.async (overlaps with P conversion below)
#pragma unroll
        for (int i = 0; i < 12; i++) {
            int idx = i * 256 + tid;
            int n = idx >> 4, c16 = idx & 15;
            int g = n * 128 + (k0 >> 3) + c16;
            uint32_t so2 = (uint32_t)(n * O_LD + c16 * 8) * 2;
            cp_async16(svh_u + so2, Vh4 + g);
            cp_async16(svl_u + so2, Vl4 + g);
        }
        CP_COMMIT();
        // P: 128 rows x 128 fp32 -> bf16 hi/lo
#pragma unroll
        for (int i = 0; i < 8; i++) {
            int idx = i * 256 + tid;
            int r = idx >> 4, c8 = idx & 15;
            float4 u = Ab4[r * 256 + (k0 >> 2) + c8 * 2];
            float4 w = Ab4[r * 256 + (k0 >> 2) + c8 * 2 + 1];
            __nv_bfloat162 h0 = __float22bfloat162_rn(make_float2(u.x, u.y));
            __nv_bfloat162 h1 = __float22bfloat162_rn(make_float2(u.z, u.w));
            __nv_bfloat162 h2 = __float22bfloat162_rn(make_float2(w.x, w.y));
            __nv_bfloat162 h3 = __float22bfloat162_rn(make_float2(w.z, w.w));
            float2 f0 = __bfloat1622float2(h0), f1 = __bfloat1622float2(h1);
            float2 f2 = __bfloat1622float2(h2), f3 = __bfloat1622float2(h3);
            __nv_bfloat162 l0 = __float22bfloat162_rn(make_float2(u.x - f0.x, u.y - f0.y));
            __nv_bfloat162 l1 = __float22bfloat162_rn(make_float2(u.z - f1.x, u.w - f1.y));
            __nv_bfloat162 l2 = __float22bfloat162_rn(make_float2(w.x - f2.x, w.y - f2.y));
            __nv_bfloat162 l3 = __float22bfloat162_rn(make_float2(w.z - f3.x, w.w - f3.y));
            int so = r * O_LD + c8 * 8;
            *(uint4*)(sPh + so) = make_uint4(*(uint32_t*)&h0, *(uint32_t*)&h1, *(uint32_t*)&h2, *(uint32_t*)&h3);
            *(uint4*)(sPl + so) = make_uint4(*(uint32_t*)&l0, *(uint32_t*)&l1, *(uint32_t*)&l2, *(uint32_t*)&l3);
        }
        CP_WAIT0();
        __syncthreads();

        wmma::fragment<wmma::matrix_a, 16, 16, 16, __nv_bfloat16, wmma::row_major> ah[2], al[2];
        wmma::fragment<wmma::matrix_b, 16, 16, 16, __nv_bfloat16, wmma::col_major> bh, bl;
#pragma unroll
        for (int ks = 0; ks < 8; ks++) {
            const int kk = ks * 16;
#pragma unroll
            for (int i = 0; i < 2; i++) {
                wmma::load_matrix_sync(ah[i], sPh + (mb + i * 16) * O_LD + kk, O_LD);
                wmma::load_matrix_sync(al[i], sPl + (mb + i * 16) * O_LD + kk, O_LD);
            }
#pragma unroll
            for (int j = 0; j < 6; j++) {
                wmma::load_matrix_sync(bh, sVh + (nb + j * 16) * O_LD + kk, O_LD);
                wmma::load_matrix_sync(bl, sVl + (nb + j * 16) * O_LD + kk, O_LD);
#pragma unroll
                for (int i = 0; i < 2; i++) {
                    wmma::mma_sync(acc[i][j], ah[i], bh, acc[i][j]);
                    wmma::mma_sync(acc[i][j], ah[i], bl, acc[i][j]);
                    wmma::mma_sync(acc[i][j], al[i], bh, acc[i][j]);
                }
            }
        }
    }
    __syncthreads();

#pragma unroll
    for (int i = 0; i < 2; i++)
#pragma unroll
        for (int j = 0; j < 6; j++)
            wmma::store_matrix_sync(sOut + (mb + i * 16) * O_OLD + nb + j * 16,
                                    acc[i][j], O_OLD, wmma::mem_row_major);
    __syncthreads();

    for (int it = 0; it < 16; it++) {
        const int r = wid + it * 8;
        const float* rowp = sOut + r * O_OLD + lane * 6;
        float f[6];
#pragma unroll
        for (int e = 0; e < 6; e++) f[e] = rowp[e];
        float s = 0.f, s2 = 0.f;
#pragma unroll
        for (int e = 0; e < 6; e++) { s += f[e]; s2 += f[e] * f[e]; }
#pragma unroll
        for (int o = 16; o; o >>= 1) {
            s  += __shfl_xor_sync(0xffffffffu, s, o);
            s2 += __shfl_xor_sync(0xffffffffu, s2, o);
        }
        float mean = s * (1.f / 192.f);
        float var  = s2 * (1.f / 192.f) - mean * mean;
        float rstd = rsqrtf(var + 1e-5f);
        float* orow = O + (size_t)(b * SEQ + m0 + r) * DQK + lane * 6;
#pragma unroll
        for (int e = 0; e < 6; e += 2) {
            float2 w;
            w.x = (f[e]     - mean) * rstd * sg[lane * 6 + e]     + sbt[lane * 6 + e];
            w.y = (f[e + 1] - mean) * rstd * sg[lane * 6 + e + 1] + sbt[lane * 6 + e + 1];
            *(float2*)(orow + e) = w;
        }
    }
}

// ---------------- launch ----------------
extern "C" void kernel_launch(void* const* d_in, const int* in_sizes, int n_in,
                              void* d_out, int out_size) {
    const float* x     = (const float*)d_in[0];
    const float* w     = (const float*)d_in[1];
    const float* ew    = (const float*)d_in[2];
    const float* tw    = (const float*)d_in[3];
    const float* gamma = (const float*)d_in[4];
    const float* beta  = (const float*)d_in[5];
    (void)in_sizes; (void)n_in; (void)out_size;

    float* out      = (float*)d_out;
    float* out_o    = out;                                  // [16,1024,192]
    float* out_attn = out + (size_t)NTOK * DQK;             // [16,1024,1024]

    cudaFuncSetAttribute(scores_wmma, cudaFuncAttributeMaxDynamicSharedMemorySize, SC_SMEM);
    cudaFuncSetAttribute(o_wmma,      cudaFuncAttributeMaxDynamicSharedMemorySize, O_SMEM);

    build_U_kernel<<<48, 16>>>(w, ew, tw);
    qkv_kernel<<<dim3(16, NTOK / 128), 128>>>(x);
    scores_wmma<<<dim3(8, 8, 16), 256, SC_SMEM>>>(out_attn);
    softmax_kernel<<<NTOK, 256>>>(out_attn);
    o_wmma<<<dim3(8, 16), 256, O_SMEM>>>(out_attn, out_o, gamma, beta);
}